// round 1
// baseline (speedup 1.0000x reference)
#include <cuda_runtime.h>
#include <cstdint>
#include <cstdio>

#define B_SZ 512
#define T_SZ 128

// Module dims (padded D to multiple of 16 for the K loop):
//   m0: D=300 (pad 304), H=256, G=1024
//   m1: D= 74 (pad  80), H= 64, G= 256
//   m2: D= 35 (pad  48), H= 64, G= 256

// ---------------- __device__ scratch (no allocations allowed) ----------------
__device__ __align__(128) float g_xg0[(size_t)T_SZ * B_SZ * 1024]; // 268 MB
__device__ __align__(128) float g_xg1[(size_t)T_SZ * B_SZ * 256];  //  67 MB
__device__ __align__(128) float g_xg2[(size_t)T_SZ * B_SZ * 256];  //  67 MB
__device__ __align__(128) float g_wih0[1024 * 304];
__device__ __align__(128) float g_wih1[256 * 80];
__device__ __align__(128) float g_wih2[256 * 48];
__device__ __align__(128) float g_whh0[1024 * 256];
__device__ __align__(128) float g_whh1[256 * 64];
__device__ __align__(128) float g_whh2[256 * 64];
__device__ __align__(128) float g_bias0[1024];
__device__ __align__(128) float g_bias1[256];
__device__ __align__(128) float g_bias2[256];
__device__ __align__(128) float g_h0[2][B_SZ * 256];
__device__ __align__(128) float g_h1[2][B_SZ * 64];
__device__ __align__(128) float g_h2[2][B_SZ * 64];
__device__ __align__(128) float g_c0[B_SZ * 256];
__device__ __align__(128) float g_c1[B_SZ * 64];
__device__ __align__(128) float g_c2[B_SZ * 64];

// ---------------- helpers ----------------
__device__ __forceinline__ float tf32r(float x) {
    uint32_t u;
    asm("cvt.rna.tf32.f32 %0, %1;" : "=r"(u) : "f"(x));
    return __uint_as_float(u);
}

__device__ __forceinline__ void mma_tf32(float c[4], const uint32_t a[4], const uint32_t b[2]) {
    asm volatile(
        "mma.sync.aligned.m16n8k8.row.col.f32.tf32.tf32.f32 "
        "{%0,%1,%2,%3}, {%4,%5,%6,%7}, {%8,%9}, {%0,%1,%2,%3};"
        : "+f"(c[0]), "+f"(c[1]), "+f"(c[2]), "+f"(c[3])
        : "r"(a[0]), "r"(a[1]), "r"(a[2]), "r"(a[3]), "r"(b[0]), "r"(b[1]));
}

__device__ __forceinline__ float sigm(float x) { return 1.0f / (1.0f + expf(-x)); }

// ---------------- prep: reorder rows to gate-interleaved g' = 4k+q, tf32-round ----------------
__global__ void prep_kernel(
    const float* __restrict__ wih0, const float* __restrict__ whh0,
    const float* __restrict__ bih0, const float* __restrict__ bhh0,
    const float* __restrict__ wih1, const float* __restrict__ whh1,
    const float* __restrict__ bih1, const float* __restrict__ bhh1,
    const float* __restrict__ wih2, const float* __restrict__ whh2,
    const float* __restrict__ bih2, const float* __restrict__ bhh2)
{
    int stride = gridDim.x * blockDim.x;
    int t0 = blockIdx.x * blockDim.x + threadIdx.x;

    for (int i = t0; i < 1024 * 304; i += stride) {
        int gp = i / 304, dp = i - gp * 304;
        int k = gp >> 2, q = gp & 3, go = q * 256 + k;
        g_wih0[i] = (dp < 300) ? tf32r(wih0[go * 300 + dp]) : 0.0f;
    }
    for (int i = t0; i < 256 * 80; i += stride) {
        int gp = i / 80, dp = i - gp * 80;
        int k = gp >> 2, q = gp & 3, go = q * 64 + k;
        g_wih1[i] = (dp < 74) ? tf32r(wih1[go * 74 + dp]) : 0.0f;
    }
    for (int i = t0; i < 256 * 48; i += stride) {
        int gp = i / 48, dp = i - gp * 48;
        int k = gp >> 2, q = gp & 3, go = q * 64 + k;
        g_wih2[i] = (dp < 35) ? tf32r(wih2[go * 35 + dp]) : 0.0f;
    }
    for (int i = t0; i < 1024 * 256; i += stride) {
        int gp = i >> 8, dp = i & 255;
        int k = gp >> 2, q = gp & 3, go = q * 256 + k;
        g_whh0[i] = tf32r(whh0[go * 256 + dp]);
    }
    for (int i = t0; i < 256 * 64; i += stride) {
        int gp = i >> 6, dp = i & 63;
        int k = gp >> 2, q = gp & 3, go = q * 64 + k;
        g_whh1[i] = tf32r(whh1[go * 64 + dp]);
        g_whh2[i] = tf32r(whh2[go * 64 + dp]);
    }
    for (int i = t0; i < 1024; i += stride) {
        int k = i >> 2, q = i & 3, go = q * 256 + k;
        g_bias0[i] = bih0[go] + bhh0[go];
    }
    for (int i = t0; i < 256; i += stride) {
        int k = i >> 2, q = i & 3, go = q * 64 + k;
        g_bias1[i] = bih1[go] + bhh1[go];
        g_bias2[i] = bih2[go] + bhh2[go];
    }
}

// ---------------- input projection GEMM: xg[t][b][g'] = x @ W'^T + bias' ----------------
// C[N=65536, G], row n = b*T + t. Block tile 64x64, K-tile 16. 256 threads, 8 warps (2m x 4n).
template <int MOD>
__global__ void proj_kernel(const float* __restrict__ X) {
    constexpr int D  = (MOD == 0) ? 300 : (MOD == 1 ? 74 : 35);
    constexpr int DP = (MOD == 0) ? 304 : (MOD == 1 ? 80 : 48);
    constexpr int G  = (MOD == 0) ? 1024 : 256;
    const float* W    = (MOD == 0) ? g_wih0 : (MOD == 1 ? g_wih1 : g_wih2);
    const float* bias = (MOD == 0) ? g_bias0 : (MOD == 1 ? g_bias1 : g_bias2);
    float* XG         = (MOD == 0) ? g_xg0 : (MOD == 1 ? g_xg1 : g_xg2);

    __shared__ __align__(16) float xs[64 * 20];
    __shared__ __align__(16) float ws[64 * 20];

    int tid = threadIdx.x, lane = tid & 31, warp = tid >> 5;
    int gp = lane >> 2, tg = lane & 3;
    int wm = warp >> 2, wn = warp & 3; // 2 x 4
    int rowBase = blockIdx.y * 64;
    int colBase = blockIdx.x * 64;
    int lr = tid >> 2, lc = tid & 3;

    float acc[2][2][4];
#pragma unroll
    for (int i = 0; i < 2; i++)
#pragma unroll
        for (int j = 0; j < 2; j++)
#pragma unroll
            for (int v = 0; v < 4; v++) acc[i][j][v] = 0.0f;

    for (int k0 = 0; k0 < DP; k0 += 16) {
        {
            int grow = rowBase + lr;
            int db = k0 + lc * 4;
            const float* xp = X + (size_t)grow * D + db;
            float4 v;
            v.x = (db + 0 < D) ? tf32r(xp[0]) : 0.0f;
            v.y = (db + 1 < D) ? tf32r(xp[1]) : 0.0f;
            v.z = (db + 2 < D) ? tf32r(xp[2]) : 0.0f;
            v.w = (db + 3 < D) ? tf32r(xp[3]) : 0.0f;
            *(float4*)&xs[lr * 20 + lc * 4] = v;
            float4 wv = *(const float4*)&W[(colBase + lr) * DP + k0 + lc * 4];
            *(float4*)&ws[lr * 20 + lc * 4] = wv;
        }
        __syncthreads();
#pragma unroll
        for (int kk = 0; kk < 2; kk++) {
            uint32_t a[2][4], b[2][2];
#pragma unroll
            for (int mt = 0; mt < 2; mt++) {
                int ar = (wm * 32 + mt * 16 + gp) * 20 + kk * 8 + tg;
                a[mt][0] = __float_as_uint(xs[ar]);
                a[mt][1] = __float_as_uint(xs[ar + 160]);
                a[mt][2] = __float_as_uint(xs[ar + 4]);
                a[mt][3] = __float_as_uint(xs[ar + 164]);
            }
#pragma unroll
            for (int nt = 0; nt < 2; nt++) {
                int br = (wn * 16 + nt * 8 + gp) * 20 + kk * 8 + tg;
                b[nt][0] = __float_as_uint(ws[br]);
                b[nt][1] = __float_as_uint(ws[br + 4]);
            }
#pragma unroll
            for (int mt = 0; mt < 2; mt++)
#pragma unroll
                for (int nt = 0; nt < 2; nt++) mma_tf32(acc[mt][nt], a[mt], b[nt]);
        }
        __syncthreads();
    }

#pragma unroll
    for (int mt = 0; mt < 2; mt++)
#pragma unroll
        for (int nt = 0; nt < 2; nt++) {
            int r0 = rowBase + wm * 32 + mt * 16 + gp;
            int col = colBase + wn * 16 + nt * 8 + 2 * tg;
            float bx = bias[col], by = bias[col + 1];
            int tt0 = r0 & 127, bb0 = r0 >> 7;
            float2 o0 = make_float2(acc[mt][nt][0] + bx, acc[mt][nt][1] + by);
            *(float2*)&XG[((size_t)tt0 * B_SZ + bb0) * G + col] = o0;
            int r1 = r0 + 8;
            int tt1 = r1 & 127, bb1 = r1 >> 7;
            float2 o1 = make_float2(acc[mt][nt][2] + bx, acc[mt][nt][3] + by);
            *(float2*)&XG[((size_t)tt1 * B_SZ + bb1) * G + col] = o1;
        }
}

// ---------------- init h(0), c = 0 ----------------
__global__ void init_kernel() {
    int stride = gridDim.x * blockDim.x;
    int i0 = blockIdx.x * blockDim.x + threadIdx.x;
    for (int i = i0; i < B_SZ * 256; i += stride) { g_h0[0][i] = 0.0f; g_c0[i] = 0.0f; }
    for (int i = i0; i < B_SZ * 64; i += stride) {
        g_h1[0][i] = 0.0f; g_c1[i] = 0.0f;
        g_h2[0][i] = 0.0f; g_c2[i] = 0.0f;
    }
}

// ---------------- one recurrent step (all 3 modules fused; 128 blocks, 1 wave) ----------------
// gates[B, 4H'] = h @ W_hh'^T + xg[t];  then elementwise LSTM cell update.
// m0: 64 blocks (8 batch-tiles x 8 gate-col tiles of 128)
// m1: 32 blocks (8 x 4 tiles of 64), m2: 32 blocks.
__global__ void step_kernel(int t, int par) {
    __shared__ __align__(16) float pool[8192]; // staging (<=3840 floats) then gates (<=8192)

    int bid = blockIdx.x;
    int H, G, BN, units, NT, ush, bm, bn;
    const float *whh, *xg, *hin;
    float *hout, *cc;
    if (bid < 64) {
        H = 256; G = 1024; BN = 128; units = 32; NT = 4; ush = 5;
        bm = bid >> 3; bn = bid & 7;
        whh = g_whh0; xg = g_xg0 + (size_t)t * B_SZ * 1024;
        hin = g_h0[par]; hout = g_h0[par ^ 1]; cc = g_c0;
    } else if (bid < 96) {
        int r = bid - 64;
        H = 64; G = 256; BN = 64; units = 16; NT = 2; ush = 4;
        bm = r >> 2; bn = r & 3;
        whh = g_whh1; xg = g_xg1 + (size_t)t * B_SZ * 256;
        hin = g_h1[par]; hout = g_h1[par ^ 1]; cc = g_c1;
    } else {
        int r = bid - 96;
        H = 64; G = 256; BN = 64; units = 16; NT = 2; ush = 4;
        bm = r >> 2; bn = r & 3;
        whh = g_whh2; xg = g_xg2 + (size_t)t * B_SZ * 256;
        hin = g_h2[par]; hout = g_h2[par ^ 1]; cc = g_c2;
    }
    int rowBase = bm * 64;
    int colBase = bn * BN;

    int tid = threadIdx.x, lane = tid & 31, warp = tid >> 5;
    int gp = lane >> 2, tg = lane & 3;
    int wm = warp >> 2, wn = warp & 3; // 2 x 4
    int wcw = BN >> 2;                 // warp col width: 32 or 16
    int lr = tid >> 2, lc = tid & 3;

    float* hs = pool;         // 64 x 20
    float* wsm = pool + 1280; // BN x 20

    float acc[2][4][4];
#pragma unroll
    for (int i = 0; i < 2; i++)
#pragma unroll
        for (int j = 0; j < 4; j++)
#pragma unroll
            for (int v = 0; v < 4; v++) acc[i][j][v] = 0.0f;

    for (int k0 = 0; k0 < H; k0 += 16) {
        {
            float4 hv = *(const float4*)&hin[(rowBase + lr) * H + k0 + lc * 4];
            hv.x = tf32r(hv.x); hv.y = tf32r(hv.y); hv.z = tf32r(hv.z); hv.w = tf32r(hv.w);
            *(float4*)&hs[lr * 20 + lc * 4] = hv;
        }
        for (int i = tid; i < BN * 4; i += 256) {
            int r = i >> 2, c = i & 3;
            *(float4*)&wsm[r * 20 + c * 4] =
                *(const float4*)&whh[(colBase + r) * H + k0 + c * 4];
        }
        __syncthreads();
#pragma unroll
        for (int kk = 0; kk < 2; kk++) {
            uint32_t a[2][4], b[4][2];
#pragma unroll
            for (int mt = 0; mt < 2; mt++) {
                int ar = (wm * 32 + mt * 16 + gp) * 20 + kk * 8 + tg;
                a[mt][0] = __float_as_uint(hs[ar]);
                a[mt][1] = __float_as_uint(hs[ar + 160]);
                a[mt][2] = __float_as_uint(hs[ar + 4]);
                a[mt][3] = __float_as_uint(hs[ar + 164]);
            }
            for (int nt = 0; nt < NT; nt++) {
                int br = (wn * wcw + nt * 8 + gp) * 20 + kk * 8 + tg;
                b[nt][0] = __float_as_uint(wsm[br]);
                b[nt][1] = __float_as_uint(wsm[br + 4]);
            }
#pragma unroll
            for (int mt = 0; mt < 2; mt++)
                for (int nt = 0; nt < NT; nt++) mma_tf32(acc[mt][nt], a[mt], b[nt]);
        }
        __syncthreads();
    }

    // gates -> smem (overwrites staging; all reads done, sync above guards)
    float* gsm = pool;
    for (int mt = 0; mt < 2; mt++)
        for (int nt = 0; nt < NT; nt++) {
            int r = wm * 32 + mt * 16 + gp;
            int col = wn * wcw + nt * 8 + 2 * tg;
            *(float2*)&gsm[r * BN + col] = make_float2(acc[mt][nt][0], acc[mt][nt][1]);
            *(float2*)&gsm[(r + 8) * BN + col] = make_float2(acc[mt][nt][2], acc[mt][nt][3]);
        }
    __syncthreads();

    // pointwise LSTM cell update: cols 4k..4k+3 = (i,f,g,o) of hidden unit k
    int items = 64 * units;
    for (int idx = tid; idx < items; idx += 256) {
        int bl = idx >> ush, kl = idx & (units - 1);
        float4 gt = *(float4*)&gsm[bl * BN + 4 * kl];
        int bg = rowBase + bl;
        int kg = bn * units + kl;
        float4 xv = *(const float4*)&xg[(size_t)bg * G + colBase + 4 * kl];
        float pi = gt.x + xv.x, pf = gt.y + xv.y, pg = gt.z + xv.z, po = gt.w + xv.w;
        float ii = sigm(pi), ff = sigm(pf), gg = tanhf(pg), oo = sigm(po);
        float cold = cc[bg * H + kg];
        float cn = ff * cold + ii * gg;
        float hn = oo * tanhf(cn);
        cc[bg * H + kg] = cn;
        hout[bg * H + kg] = hn;
    }
}

// ---------------- head: out = relu(concat(h) @ w1^T + b1) @ w2^T + b2 ----------------
__global__ void head_kernel(const float* __restrict__ w1, const float* __restrict__ b1,
                            const float* __restrict__ w2, const float* __restrict__ b2,
                            float* __restrict__ out) {
    __shared__ float hc[8 * 384];
    __shared__ float red[256];
    int tid = threadIdx.x;
    int rowBase = blockIdx.x * 8;

    for (int i = tid; i < 8 * 384; i += 256) {
        int r = i / 384, d = i - r * 384;
        int bg = rowBase + r;
        float v;
        if (d < 256)      v = g_h0[0][bg * 256 + d];
        else if (d < 320) v = g_h1[0][bg * 64 + (d - 256)];
        else              v = g_h2[0][bg * 64 + (d - 320)];
        hc[i] = v;
    }
    __syncthreads();

    for (int pass = 0; pass < 2; pass++) {
        int row = pass * 4 + (tid >> 6);
        int cell = tid & 63;
        const float* wr = w1 + cell * 384;
        const float* hr = hc + row * 384;
        float a = b1[cell];
#pragma unroll 4
        for (int d = 0; d < 384; d++) a += hr[d] * wr[d];
        a = fmaxf(a, 0.0f);
        red[tid] = a * w2[cell];
        __syncthreads();
        if (cell == 0) {
            float s = 0.0f;
#pragma unroll
            for (int j = 0; j < 64; j++) s += red[tid + j];
            out[rowBase + row] = s + b2[0];
        }
        __syncthreads();
    }
}

// ---------------- launch ----------------
extern "C" void kernel_launch(void* const* d_in, const int* in_sizes, int n_in,
                              void* d_out, int out_size) {
    const float* x0    = (const float*)d_in[0];
    const float* x1    = (const float*)d_in[1];
    const float* x2    = (const float*)d_in[2];
    const float* w_ih0 = (const float*)d_in[3];
    const float* w_hh0 = (const float*)d_in[4];
    const float* b_ih0 = (const float*)d_in[5];
    const float* b_hh0 = (const float*)d_in[6];
    const float* w_ih1 = (const float*)d_in[7];
    const float* w_hh1 = (const float*)d_in[8];
    const float* b_ih1 = (const float*)d_in[9];
    const float* b_hh1 = (const float*)d_in[10];
    const float* w_ih2 = (const float*)d_in[11];
    const float* w_hh2 = (const float*)d_in[12];
    const float* b_ih2 = (const float*)d_in[13];
    const float* b_hh2 = (const float*)d_in[14];
    const float* w1    = (const float*)d_in[15];
    const float* b1    = (const float*)d_in[16];
    const float* w2    = (const float*)d_in[17];
    const float* b2    = (const float*)d_in[18];
    float* out = (float*)d_out;

    prep_kernel<<<512, 256>>>(w_ih0, w_hh0, b_ih0, b_hh0,
                              w_ih1, w_hh1, b_ih1, b_hh1,
                              w_ih2, w_hh2, b_ih2, b_hh2);

    proj_kernel<0><<<dim3(16, 1024), 256>>>(x0);
    proj_kernel<1><<<dim3(4, 1024), 256>>>(x1);
    proj_kernel<2><<<dim3(4, 1024), 256>>>(x2);

    init_kernel<<<256, 256>>>();

    for (int t = 0; t < T_SZ; t++) {
        step_kernel<<<128, 256>>>(t, t & 1);
    }

    head_kernel<<<64, 256>>>(w1, b1, w2, b2, out);
}

// round 2
// speedup vs baseline: 1.4277x; 1.4277x over previous
#include <cuda_runtime.h>
#include <cstdint>

#define B_SZ 512
#define T_SZ 128
#define NBLK 144
#define SMEM_PERSIST 166400

// ---------------- __device__ scratch (no allocations allowed) ----------------
__device__ __align__(128) float g_xg0[(size_t)T_SZ * B_SZ * 1024];
__device__ __align__(128) float g_xg1[(size_t)T_SZ * B_SZ * 256];
__device__ __align__(128) float g_xg2[(size_t)T_SZ * B_SZ * 256];
__device__ __align__(128) float g_xp0[(size_t)65536 * 304];
__device__ __align__(128) float g_xp1[(size_t)65536 * 80];
__device__ __align__(128) float g_xp2[(size_t)65536 * 48];
__device__ __align__(128) float g_wih0[1024 * 304];
__device__ __align__(128) float g_wih1[256 * 80];
__device__ __align__(128) float g_wih2[256 * 48];
__device__ __align__(128) float g_whh0[1024 * 256];
__device__ __align__(128) float g_whh1[256 * 64];
__device__ __align__(128) float g_whh2[256 * 64];
__device__ __align__(128) float g_bias0[1024];
__device__ __align__(128) float g_bias1[256];
__device__ __align__(128) float g_bias2[256];
__device__ __align__(128) float g_h0[2][B_SZ * 256];
__device__ __align__(128) float g_h1[2][B_SZ * 64];
__device__ __align__(128) float g_h2[2][B_SZ * 64];
__device__ __align__(128) float g_c0[B_SZ * 256];
__device__ __align__(128) float g_c1[B_SZ * 64];
__device__ __align__(128) float g_c2[B_SZ * 64];
__device__ unsigned g_bar;

// ---------------- helpers ----------------
__device__ __forceinline__ float tf32r(float x) {
    uint32_t u;
    asm("cvt.rna.tf32.f32 %0, %1;" : "=r"(u) : "f"(x));
    return __uint_as_float(u);
}

__device__ __forceinline__ void mma_tf32(float c[4], const uint32_t a[4], const uint32_t b[2]) {
    asm volatile(
        "mma.sync.aligned.m16n8k8.row.col.f32.tf32.tf32.f32 "
        "{%0,%1,%2,%3}, {%4,%5,%6,%7}, {%8,%9}, {%0,%1,%2,%3};"
        : "+f"(c[0]), "+f"(c[1]), "+f"(c[2]), "+f"(c[3])
        : "r"(a[0]), "r"(a[1]), "r"(a[2]), "r"(a[3]), "r"(b[0]), "r"(b[1]));
}

__device__ __forceinline__ float sigm(float x) { return 1.0f / (1.0f + expf(-x)); }

__device__ __forceinline__ void cpasync16(void* dst, const void* src) {
    uint32_t d = (uint32_t)__cvta_generic_to_shared(dst);
    asm volatile("cp.async.ca.shared.global [%0], [%1], 16;" :: "r"(d), "l"(src));
}
#define CP_COMMIT asm volatile("cp.async.commit_group;")
#define CP_WAIT1  asm volatile("cp.async.wait_group 1;")
#define CP_WAIT0  asm volatile("cp.async.wait_group 0;")

// grid-wide barrier: arrive + spin (CG grid.sync pattern)
__device__ __forceinline__ void grid_bar(int tid, unsigned target) {
    __syncthreads();
    if (tid == 0) {
        __threadfence();
        atomicAdd(&g_bar, 1u);
        while (*(volatile unsigned*)&g_bar < target) __nanosleep(20);
        __threadfence();
    }
    __syncthreads();
}

// ---------------- prep: reorder rows to gate-interleaved g' = 4k+q, tf32-round ----------------
__global__ void prep_kernel(
    const float* __restrict__ wih0, const float* __restrict__ whh0,
    const float* __restrict__ bih0, const float* __restrict__ bhh0,
    const float* __restrict__ wih1, const float* __restrict__ whh1,
    const float* __restrict__ bih1, const float* __restrict__ bhh1,
    const float* __restrict__ wih2, const float* __restrict__ whh2,
    const float* __restrict__ bih2, const float* __restrict__ bhh2)
{
    int stride = gridDim.x * blockDim.x;
    int t0 = blockIdx.x * blockDim.x + threadIdx.x;

    for (int i = t0; i < 1024 * 304; i += stride) {
        int gp = i / 304, dp = i - gp * 304;
        int k = gp >> 2, q = gp & 3, go = q * 256 + k;
        g_wih0[i] = (dp < 300) ? tf32r(wih0[go * 300 + dp]) : 0.0f;
    }
    for (int i = t0; i < 256 * 80; i += stride) {
        int gp = i / 80, dp = i - gp * 80;
        int k = gp >> 2, q = gp & 3, go = q * 64 + k;
        g_wih1[i] = (dp < 74) ? tf32r(wih1[go * 74 + dp]) : 0.0f;
    }
    for (int i = t0; i < 256 * 48; i += stride) {
        int gp = i / 48, dp = i - gp * 48;
        int k = gp >> 2, q = gp & 3, go = q * 64 + k;
        g_wih2[i] = (dp < 35) ? tf32r(wih2[go * 35 + dp]) : 0.0f;
    }
    for (int i = t0; i < 1024 * 256; i += stride) {
        int gp = i >> 8, dp = i & 255;
        int k = gp >> 2, q = gp & 3, go = q * 256 + k;
        g_whh0[i] = tf32r(whh0[go * 256 + dp]);
    }
    for (int i = t0; i < 256 * 64; i += stride) {
        int gp = i >> 6, dp = i & 63;
        int k = gp >> 2, q = gp & 3, go = q * 64 + k;
        g_whh1[i] = tf32r(whh1[go * 64 + dp]);
        g_whh2[i] = tf32r(whh2[go * 64 + dp]);
    }
    for (int i = t0; i < 1024; i += stride) {
        int k = i >> 2, q = i & 3, go = q * 256 + k;
        g_bias0[i] = bih0[go] + bhh0[go];
    }
    for (int i = t0; i < 256; i += stride) {
        int k = i >> 2, q = i & 3, go = q * 64 + k;
        g_bias1[i] = bih1[go] + bhh1[go];
        g_bias2[i] = bih2[go] + bhh2[go];
    }
}

// ---------------- pad x -> xp (tf32-rounded, zero-padded K) ----------------
template <int MOD>
__global__ void pad_kernel(const float* __restrict__ X) {
    constexpr int D  = (MOD == 0) ? 300 : (MOD == 1 ? 74 : 35);
    constexpr int DP = (MOD == 0) ? 304 : (MOD == 1 ? 80 : 48);
    float* XP = (MOD == 0) ? g_xp0 : (MOD == 1 ? g_xp1 : g_xp2);
    size_t n = (size_t)65536 * DP;
    size_t stride = (size_t)gridDim.x * blockDim.x;
    for (size_t i = (size_t)blockIdx.x * blockDim.x + threadIdx.x; i < n; i += stride) {
        int r = (int)(i / DP);
        int d = (int)(i - (size_t)r * DP);
        XP[i] = (d < D) ? tf32r(X[(size_t)r * D + d]) : 0.0f;
    }
}

// ---------------- input projection GEMM: xg[t][b][g'] = xp @ W'^T + bias' ----------------
// 128x128 block tile, 2-stage cp.async pipeline, 256 threads (4m x 2n warps).
template <int MOD>
__global__ __launch_bounds__(256) void proj_kernel() {
    constexpr int DP = (MOD == 0) ? 304 : (MOD == 1 ? 80 : 48);
    constexpr int G  = (MOD == 0) ? 1024 : 256;
    constexpr int KT = DP / 16;
    const float* XP   = (MOD == 0) ? g_xp0 : (MOD == 1 ? g_xp1 : g_xp2);
    const float* W    = (MOD == 0) ? g_wih0 : (MOD == 1 ? g_wih1 : g_wih2);
    const float* bias = (MOD == 0) ? g_bias0 : (MOD == 1 ? g_bias1 : g_bias2);
    float* XG         = (MOD == 0) ? g_xg0 : (MOD == 1 ? g_xg1 : g_xg2);

    __shared__ __align__(16) float xs[2][128 * 20];
    __shared__ __align__(16) float ws[2][128 * 20];

    int tid = threadIdx.x, lane = tid & 31, warp = tid >> 5;
    int gp = lane >> 2, tg = lane & 3;
    int wm = warp >> 1, wn = warp & 1; // 4 x 2
    int rowBase = blockIdx.y * 128;
    int colBase = blockIdx.x * 128;

    float acc[2][8][4];
#pragma unroll
    for (int i = 0; i < 2; i++)
#pragma unroll
        for (int j = 0; j < 8; j++)
#pragma unroll
            for (int v = 0; v < 4; v++) acc[i][j][v] = 0.0f;

    // stage issue: 512 x-chunks + 512 w-chunks of 16B
    auto issue = [&](int kt, int s) {
        int k0 = kt * 16;
#pragma unroll
        for (int j = 0; j < 2; j++) {
            int id = tid + j * 256;
            int r = id >> 2, c = id & 3;
            cpasync16(&xs[s][r * 20 + c * 4], &XP[(size_t)(rowBase + r) * DP + k0 + c * 4]);
            cpasync16(&ws[s][r * 20 + c * 4], &W[(size_t)(colBase + r) * DP + k0 + c * 4]);
        }
    };

    issue(0, 0);
    CP_COMMIT;

    for (int kt = 0; kt < KT; kt++) {
        int s = kt & 1;
        if (kt + 1 < KT) {
            issue(kt + 1, s ^ 1);
            CP_COMMIT;
            CP_WAIT1;
        } else {
            CP_WAIT0;
        }
        __syncthreads();
#pragma unroll
        for (int kk = 0; kk < 2; kk++) {
            uint32_t a[2][4];
#pragma unroll
            for (int mt = 0; mt < 2; mt++) {
                int ar = (wm * 32 + mt * 16 + gp) * 20 + kk * 8 + tg;
                a[mt][0] = __float_as_uint(xs[s][ar]);
                a[mt][1] = __float_as_uint(xs[s][ar + 160]);
                a[mt][2] = __float_as_uint(xs[s][ar + 4]);
                a[mt][3] = __float_as_uint(xs[s][ar + 164]);
            }
#pragma unroll
            for (int nt = 0; nt < 8; nt++) {
                int br = (wn * 64 + nt * 8 + gp) * 20 + kk * 8 + tg;
                uint32_t b[2];
                b[0] = __float_as_uint(ws[s][br]);
                b[1] = __float_as_uint(ws[s][br + 4]);
#pragma unroll
                for (int mt = 0; mt < 2; mt++) mma_tf32(acc[mt][nt], a[mt], b);
            }
        }
        __syncthreads();
    }

#pragma unroll
    for (int mt = 0; mt < 2; mt++)
#pragma unroll
        for (int nt = 0; nt < 8; nt++) {
            int r0 = rowBase + wm * 32 + mt * 16 + gp;
            int col = colBase + wn * 64 + nt * 8 + 2 * tg;
            float bx = bias[col], by = bias[col + 1];
            int tt0 = r0 & 127, bb0 = r0 >> 7;
            *(float2*)&XG[((size_t)tt0 * B_SZ + bb0) * G + col] =
                make_float2(acc[mt][nt][0] + bx, acc[mt][nt][1] + by);
            int r1 = r0 + 8;
            int tt1 = r1 & 127, bb1 = r1 >> 7;
            *(float2*)&XG[((size_t)tt1 * B_SZ + bb1) * G + col] =
                make_float2(acc[mt][nt][2] + bx, acc[mt][nt][3] + by);
        }
}

// ---------------- init h(0), c = 0, barrier counter ----------------
__global__ void init_kernel() {
    int stride = gridDim.x * blockDim.x;
    int i0 = blockIdx.x * blockDim.x + threadIdx.x;
    if (i0 == 0) g_bar = 0;
    for (int i = i0; i < B_SZ * 256; i += stride) { g_h0[0][i] = 0.0f; g_c0[i] = 0.0f; }
    for (int i = i0; i < B_SZ * 64; i += stride) {
        g_h1[0][i] = 0.0f; g_c1[i] = 0.0f;
        g_h2[0][i] = 0.0f; g_c2[i] = 0.0f;
    }
}

// ---------------- persistent recurrence: weights SMEM-resident, grid barrier per step ----
// blocks 0..127  : m0 (16 batch tiles x 32 rows) x (8 col tiles x 128 gate cols)
// blocks 128..135: m1 (8 batch tiles x 64 rows), full 256 gate cols
// blocks 136..143: m2 same
__global__ __launch_bounds__(256, 1) void persist_kernel() {
    extern __shared__ __align__(16) float sm[];
    int bid = blockIdx.x, tid = threadIdx.x;
    int lane = tid & 31, warp = tid >> 5;
    int gp = lane >> 2, tg = lane & 3;

    if (bid < 128) {
        // ================= module 0: H=256, G=1024 =================
        int bm = bid >> 3, bn = bid & 7;
        int rowBase = bm * 32, colBase = bn * 128;
        float* ws = sm;              // 128 x 260
        float* hs = sm + 128 * 260;  // 32 x 260, reused as gates 32x128

        for (int idx = tid; idx < 128 * 64; idx += 256) {
            int r = idx >> 6, c = idx & 63;
            *(float4*)&ws[r * 260 + c * 4] =
                *(const float4*)&g_whh0[(colBase + r) * 256 + c * 4];
        }

        int wm = warp >> 2, wn = warp & 3; // 2m x 4n: 16-row x 32-col warp tile

        for (int t = 0; t < T_SZ; t++) {
            const float* hin = g_h0[t & 1];
            float* hout = g_h0[(t & 1) ^ 1];
            const float* xg = g_xg0 + (size_t)t * B_SZ * 1024;

            for (int idx = tid; idx < 32 * 64; idx += 256) {
                int r = idx >> 6, c = idx & 63;
                float4 v = __ldcg((const float4*)&hin[(rowBase + r) * 256 + c * 4]);
                v.x = tf32r(v.x); v.y = tf32r(v.y); v.z = tf32r(v.z); v.w = tf32r(v.w);
                *(float4*)&hs[r * 260 + c * 4] = v;
            }
            __syncthreads();

            float acc[4][4];
#pragma unroll
            for (int j = 0; j < 4; j++)
#pragma unroll
                for (int v = 0; v < 4; v++) acc[j][v] = 0.0f;

#pragma unroll
            for (int kk = 0; kk < 32; kk++) {
                int ar = (wm * 16 + gp) * 260 + kk * 8 + tg;
                uint32_t a[4];
                a[0] = __float_as_uint(hs[ar]);
                a[1] = __float_as_uint(hs[ar + 2080]);
                a[2] = __float_as_uint(hs[ar + 4]);
                a[3] = __float_as_uint(hs[ar + 2084]);
#pragma unroll
                for (int nt = 0; nt < 4; nt++) {
                    int br = (wn * 32 + nt * 8 + gp) * 260 + kk * 8 + tg;
                    uint32_t b[2];
                    b[0] = __float_as_uint(ws[br]);
                    b[1] = __float_as_uint(ws[br + 4]);
                    mma_tf32(acc[nt], a, b);
                }
            }
            __syncthreads();

            float* gsm = hs; // 32 x 128
#pragma unroll
            for (int nt = 0; nt < 4; nt++) {
                int r = wm * 16 + gp, col = wn * 32 + nt * 8 + 2 * tg;
                *(float2*)&gsm[r * 128 + col] = make_float2(acc[nt][0], acc[nt][1]);
                *(float2*)&gsm[(r + 8) * 128 + col] = make_float2(acc[nt][2], acc[nt][3]);
            }
            __syncthreads();

            for (int idx = tid; idx < 1024; idx += 256) {
                int kl = idx & 31, bl = idx >> 5;
                float4 gt = *(float4*)&gsm[bl * 128 + 4 * kl];
                int bg = rowBase + bl;
                int kg = bn * 32 + kl;
                float4 xv = __ldg((const float4*)&xg[(size_t)bg * 1024 + colBase + 4 * kl]);
                float pi = gt.x + xv.x, pf = gt.y + xv.y, pg = gt.z + xv.z, po = gt.w + xv.w;
                float ii = sigm(pi), ff = sigm(pf), gg = tanhf(pg), oo = sigm(po);
                float cold = g_c0[bg * 256 + kg];
                float cn = ff * cold + ii * gg;
                float hn = oo * tanhf(cn);
                g_c0[bg * 256 + kg] = cn;
                __stcg(&hout[bg * 256 + kg], hn);
            }

            grid_bar(tid, (unsigned)(NBLK * (t + 1)));
        }
    } else {
        // ================= modules 1,2: H=64, G=256 =================
        int sub = bid - 128;
        int mod = sub >> 3, bm = sub & 7;
        int rowBase = bm * 64;
        const float* whh = mod ? g_whh2 : g_whh1;
        const float* xgb = mod ? g_xg2 : g_xg1;
        float* cb = mod ? g_c2 : g_c1;

        float* ws  = sm;                      // 256 x 68
        float* hs  = sm + 256 * 68;           // 64 x 68
        float* gsm = sm + 256 * 68 + 64 * 68; // 64 x 256

        for (int idx = tid; idx < 256 * 16; idx += 256) {
            int r = idx >> 4, c = idx & 15;
            *(float4*)&ws[r * 68 + c * 4] = *(const float4*)&whh[r * 64 + c * 4];
        }

        int wm = warp >> 2, wn = warp & 3; // 2m x 4n: 32-row x 64-col warp tile

        for (int t = 0; t < T_SZ; t++) {
            const float* hin = mod ? g_h2[t & 1] : g_h1[t & 1];
            float* hout = mod ? g_h2[(t & 1) ^ 1] : g_h1[(t & 1) ^ 1];
            const float* xg = xgb + (size_t)t * B_SZ * 256;

            for (int idx = tid; idx < 64 * 16; idx += 256) {
                int r = idx >> 4, c = idx & 15;
                float4 v = __ldcg((const float4*)&hin[(rowBase + r) * 64 + c * 4]);
                v.x = tf32r(v.x); v.y = tf32r(v.y); v.z = tf32r(v.z); v.w = tf32r(v.w);
                *(float4*)&hs[r * 68 + c * 4] = v;
            }
            __syncthreads();

            float acc[2][8][4];
#pragma unroll
            for (int i = 0; i < 2; i++)
#pragma unroll
                for (int j = 0; j < 8; j++)
#pragma unroll
                    for (int v = 0; v < 4; v++) acc[i][j][v] = 0.0f;

#pragma unroll
            for (int kk = 0; kk < 8; kk++) {
                uint32_t a[2][4];
#pragma unroll
                for (int mt = 0; mt < 2; mt++) {
                    int ar = (wm * 32 + mt * 16 + gp) * 68 + kk * 8 + tg;
                    a[mt][0] = __float_as_uint(hs[ar]);
                    a[mt][1] = __float_as_uint(hs[ar + 544]);
                    a[mt][2] = __float_as_uint(hs[ar + 4]);
                    a[mt][3] = __float_as_uint(hs[ar + 548]);
                }
#pragma unroll
                for (int nt = 0; nt < 8; nt++) {
                    int br = (wn * 64 + nt * 8 + gp) * 68 + kk * 8 + tg;
                    uint32_t b[2];
                    b[0] = __float_as_uint(ws[br]);
                    b[1] = __float_as_uint(ws[br + 4]);
#pragma unroll
                    for (int mt = 0; mt < 2; mt++) mma_tf32(acc[mt][nt], a[mt], b);
                }
            }

#pragma unroll
            for (int mt = 0; mt < 2; mt++)
#pragma unroll
                for (int nt = 0; nt < 8; nt++) {
                    int r = wm * 32 + mt * 16 + gp;
                    int col = wn * 64 + nt * 8 + 2 * tg;
                    *(float2*)&gsm[r * 256 + col] = make_float2(acc[mt][nt][0], acc[mt][nt][1]);
                    *(float2*)&gsm[(r + 8) * 256 + col] = make_float2(acc[mt][nt][2], acc[mt][nt][3]);
                }
            __syncthreads();

            for (int idx = tid; idx < 4096; idx += 256) {
                int kl = idx & 63, bl = idx >> 6;
                float4 gt = *(float4*)&gsm[bl * 256 + 4 * kl];
                int bg = rowBase + bl;
                float4 xv = __ldg((const float4*)&xg[(size_t)bg * 256 + 4 * kl]);
                float pi = gt.x + xv.x, pf = gt.y + xv.y, pg = gt.z + xv.z, po = gt.w + xv.w;
                float ii = sigm(pi), ff = sigm(pf), gg = tanhf(pg), oo = sigm(po);
                float cold = cb[bg * 64 + kl];
                float cn = ff * cold + ii * gg;
                float hn = oo * tanhf(cn);
                cb[bg * 64 + kl] = cn;
                __stcg(&hout[bg * 64 + kl], hn);
            }

            grid_bar(tid, (unsigned)(NBLK * (t + 1)));
        }
    }
}

// ---------------- head: out = relu(concat(h) @ w1^T + b1) @ w2^T + b2 ----------------
__global__ void head_kernel(const float* __restrict__ w1, const float* __restrict__ b1,
                            const float* __restrict__ w2, const float* __restrict__ b2,
                            float* __restrict__ out) {
    __shared__ float hc[8 * 384];
    __shared__ float red[256];
    int tid = threadIdx.x;
    int rowBase = blockIdx.x * 8;

    for (int i = tid; i < 8 * 384; i += 256) {
        int r = i / 384, d = i - r * 384;
        int bg = rowBase + r;
        float v;
        if (d < 256)      v = g_h0[0][bg * 256 + d];
        else if (d < 320) v = g_h1[0][bg * 64 + (d - 256)];
        else              v = g_h2[0][bg * 64 + (d - 320)];
        hc[i] = v;
    }
    __syncthreads();

    for (int pass = 0; pass < 2; pass++) {
        int row = pass * 4 + (tid >> 6);
        int cell = tid & 63;
        const float* wr = w1 + cell * 384;
        const float* hr = hc + row * 384;
        float a = b1[cell];
#pragma unroll 4
        for (int d = 0; d < 384; d++) a += hr[d] * wr[d];
        a = fmaxf(a, 0.0f);
        red[tid] = a * w2[cell];
        __syncthreads();
        if (cell == 0) {
            float s = 0.0f;
#pragma unroll
            for (int j = 0; j < 64; j++) s += red[tid + j];
            out[rowBase + row] = s + b2[0];
        }
        __syncthreads();
    }
}

// ---------------- launch ----------------
extern "C" void kernel_launch(void* const* d_in, const int* in_sizes, int n_in,
                              void* d_out, int out_size) {
    const float* x0    = (const float*)d_in[0];
    const float* x1    = (const float*)d_in[1];
    const float* x2    = (const float*)d_in[2];
    const float* w_ih0 = (const float*)d_in[3];
    const float* w_hh0 = (const float*)d_in[4];
    const float* b_ih0 = (const float*)d_in[5];
    const float* b_hh0 = (const float*)d_in[6];
    const float* w_ih1 = (const float*)d_in[7];
    const float* w_hh1 = (const float*)d_in[8];
    const float* b_ih1 = (const float*)d_in[9];
    const float* b_hh1 = (const float*)d_in[10];
    const float* w_ih2 = (const float*)d_in[11];
    const float* w_hh2 = (const float*)d_in[12];
    const float* b_ih2 = (const float*)d_in[13];
    const float* b_hh2 = (const float*)d_in[14];
    const float* w1    = (const float*)d_in[15];
    const float* b1    = (const float*)d_in[16];
    const float* w2    = (const float*)d_in[17];
    const float* b2    = (const float*)d_in[18];
    float* out = (float*)d_out;

    cudaFuncSetAttribute(persist_kernel, cudaFuncAttributeMaxDynamicSharedMemorySize,
                         SMEM_PERSIST);

    prep_kernel<<<512, 256>>>(w_ih0, w_hh0, b_ih0, b_hh0,
                              w_ih1, w_hh1, b_ih1, b_hh1,
                              w_ih2, w_hh2, b_ih2, b_hh2);

    pad_kernel<0><<<4096, 256>>>(x0);
    pad_kernel<1><<<2048, 256>>>(x1);
    pad_kernel<2><<<1024, 256>>>(x2);

    proj_kernel<0><<<dim3(8, 512), 256>>>();
    proj_kernel<1><<<dim3(2, 512), 256>>>();
    proj_kernel<2><<<dim3(2, 512), 256>>>();

    init_kernel<<<256, 256>>>();

    persist_kernel<<<NBLK, 256, SMEM_PERSIST>>>();

    head_kernel<<<64, 256>>>(w1, b1, w2, b2, out);
}

// round 3
// speedup vs baseline: 1.7864x; 1.2512x over previous
#include <cuda_runtime.h>
#include <cstdint>

#define B_SZ 512
#define T_SZ 128
#define NBLK 144
#define SMEM_PERSIST 223232
#define SMEM_PROJ    73728

// ---------------- __device__ scratch (no allocations allowed) ----------------
__device__ __align__(128) float g_xg0[(size_t)T_SZ * B_SZ * 1024];
__device__ __align__(128) float g_xg1[(size_t)T_SZ * B_SZ * 256];
__device__ __align__(128) float g_xg2[(size_t)T_SZ * B_SZ * 256];
__device__ __align__(128) float g_xp0[(size_t)65536 * 304]; // K pair-swizzled
__device__ __align__(128) float g_xp1[(size_t)65536 * 80];
__device__ __align__(128) float g_xp2[(size_t)65536 * 48];
__device__ __align__(128) float g_wih0[1024 * 304];         // K pair-swizzled
__device__ __align__(128) float g_wih1[256 * 80];
__device__ __align__(128) float g_wih2[256 * 48];
__device__ __align__(128) float g_whh0[1024 * 256];         // K pair-swizzled
__device__ __align__(128) float g_whh1[256 * 64];
__device__ __align__(128) float g_whh2[256 * 64];
__device__ __align__(128) float g_bias0[1024];
__device__ __align__(128) float g_bias1[256];
__device__ __align__(128) float g_bias2[256];
__device__ __align__(128) float g_h0[2][B_SZ * 256];        // hidden pair-swizzled
__device__ __align__(128) float g_h1[2][B_SZ * 64];
__device__ __align__(128) float g_h2[2][B_SZ * 64];
__device__ __align__(128) float g_c0[B_SZ * 256];
__device__ __align__(128) float g_c1[B_SZ * 64];
__device__ __align__(128) float g_c2[B_SZ * 64];
__device__ unsigned g_bar;

// ---------------- helpers ----------------
__device__ __forceinline__ int swz(int k) {
    // within each 8-group: k -> pairs (k, k+4) adjacent
    return (k & ~7) | ((k & 3) << 1) | ((k >> 2) & 1);
}

__device__ __forceinline__ float tf32r(float x) {
    uint32_t u;
    asm("cvt.rna.tf32.f32 %0, %1;" : "=r"(u) : "f"(x));
    return __uint_as_float(u);
}

__device__ __forceinline__ void mma_tf32(float c[4], const uint32_t a[4], const uint32_t b[2]) {
    asm volatile(
        "mma.sync.aligned.m16n8k8.row.col.f32.tf32.tf32.f32 "
        "{%0,%1,%2,%3}, {%4,%5,%6,%7}, {%8,%9}, {%0,%1,%2,%3};"
        : "+f"(c[0]), "+f"(c[1]), "+f"(c[2]), "+f"(c[3])
        : "r"(a[0]), "r"(a[1]), "r"(a[2]), "r"(a[3]), "r"(b[0]), "r"(b[1]));
}

__device__ __forceinline__ float sigm(float x) { return 1.0f / (1.0f + expf(-x)); }

__device__ __forceinline__ void cpasync16(void* dst, const void* src) {
    uint32_t d = (uint32_t)__cvta_generic_to_shared(dst);
    asm volatile("cp.async.ca.shared.global [%0], [%1], 16;" :: "r"(d), "l"(src));
}
#define CP_COMMIT asm volatile("cp.async.commit_group;")
#define CP_WAIT1  asm volatile("cp.async.wait_group 1;")
#define CP_WAIT0  asm volatile("cp.async.wait_group 0;")

// grid-wide barrier: arrive + spin
__device__ __forceinline__ void grid_bar(int tid, unsigned target) {
    __syncthreads();
    if (tid == 0) {
        __threadfence();
        atomicAdd(&g_bar, 1u);
        while (*(volatile unsigned*)&g_bar < target) __nanosleep(20);
        __threadfence();
    }
    __syncthreads();
}

// ---------------- launch 0: prep weights (gate-interleave + K-swizzle + tf32) + pad x ----
__global__ void prep_all_kernel(
    const float* __restrict__ x0, const float* __restrict__ x1, const float* __restrict__ x2,
    const float* __restrict__ wih0, const float* __restrict__ whh0,
    const float* __restrict__ bih0, const float* __restrict__ bhh0,
    const float* __restrict__ wih1, const float* __restrict__ whh1,
    const float* __restrict__ bih1, const float* __restrict__ bhh1,
    const float* __restrict__ wih2, const float* __restrict__ whh2,
    const float* __restrict__ bih2, const float* __restrict__ bhh2)
{
    size_t stride = (size_t)gridDim.x * blockDim.x;
    size_t t0 = (size_t)blockIdx.x * blockDim.x + threadIdx.x;

    // x pads (K pair-swizzled)
    for (size_t i = t0; i < (size_t)65536 * 304; i += stride) {
        int r = (int)(i / 304), d = (int)(i - (size_t)r * 304);
        g_xp0[(size_t)r * 304 + swz(d)] = (d < 300) ? tf32r(x0[(size_t)r * 300 + d]) : 0.0f;
    }
    for (size_t i = t0; i < (size_t)65536 * 80; i += stride) {
        int r = (int)(i / 80), d = (int)(i - (size_t)r * 80);
        g_xp1[(size_t)r * 80 + swz(d)] = (d < 74) ? tf32r(x1[(size_t)r * 74 + d]) : 0.0f;
    }
    for (size_t i = t0; i < (size_t)65536 * 48; i += stride) {
        int r = (int)(i / 48), d = (int)(i - (size_t)r * 48);
        g_xp2[(size_t)r * 48 + swz(d)] = (d < 35) ? tf32r(x2[(size_t)r * 35 + d]) : 0.0f;
    }

    // weights: gate-interleave rows g' = 4k+q, K pair-swizzle cols
    for (size_t ii = t0; ii < 1024 * 304; ii += stride) {
        int i = (int)ii;
        int gp = i / 304, dp = i - gp * 304;
        int k = gp >> 2, q = gp & 3, go = q * 256 + k;
        g_wih0[gp * 304 + swz(dp)] = (dp < 300) ? tf32r(wih0[go * 300 + dp]) : 0.0f;
    }
    for (size_t ii = t0; ii < 256 * 80; ii += stride) {
        int i = (int)ii;
        int gp = i / 80, dp = i - gp * 80;
        int k = gp >> 2, q = gp & 3, go = q * 64 + k;
        g_wih1[gp * 80 + swz(dp)] = (dp < 74) ? tf32r(wih1[go * 74 + dp]) : 0.0f;
    }
    for (size_t ii = t0; ii < 256 * 48; ii += stride) {
        int i = (int)ii;
        int gp = i / 48, dp = i - gp * 48;
        int k = gp >> 2, q = gp & 3, go = q * 64 + k;
        g_wih2[gp * 48 + swz(dp)] = (dp < 35) ? tf32r(wih2[go * 35 + dp]) : 0.0f;
    }
    for (size_t ii = t0; ii < 1024 * 256; ii += stride) {
        int i = (int)ii;
        int gp = i >> 8, dp = i & 255;
        int k = gp >> 2, q = gp & 3, go = q * 256 + k;
        g_whh0[gp * 256 + swz(dp)] = tf32r(whh0[go * 256 + dp]);
    }
    for (size_t ii = t0; ii < 256 * 64; ii += stride) {
        int i = (int)ii;
        int gp = i >> 6, dp = i & 63;
        int k = gp >> 2, q = gp & 3, go = q * 64 + k;
        g_whh1[gp * 64 + swz(dp)] = tf32r(whh1[go * 64 + dp]);
        g_whh2[gp * 64 + swz(dp)] = tf32r(whh2[go * 64 + dp]);
    }
    for (size_t ii = t0; ii < 1024; ii += stride) {
        int i = (int)ii;
        int k = i >> 2, q = i & 3, go = q * 256 + k;
        g_bias0[i] = bih0[go] + bhh0[go];
    }
    for (size_t ii = t0; ii < 256; ii += stride) {
        int i = (int)ii;
        int k = i >> 2, q = i & 3, go = q * 64 + k;
        g_bias1[i] = bih1[go] + bhh1[go];
        g_bias2[i] = bih2[go] + bhh2[go];
    }
}

// ---------------- launch 1: all input projections, 128x128 tiles, 3-stage cp.async ------
__device__ __forceinline__ void proj_impl(
    const float* __restrict__ XP, const float* __restrict__ W,
    const float* __restrict__ bias, float* __restrict__ XG,
    int DP, int G, int KT, int colBase, int rowBase, float* xs, float* ws)
{
    int tid = threadIdx.x, lane = tid & 31, warp = tid >> 5;
    int gp = lane >> 2, tg = lane & 3;
    int wm = warp >> 1, wn = warp & 1; // 4m x 2n warps

    float acc[2][8][4];
#pragma unroll
    for (int i = 0; i < 2; i++)
#pragma unroll
        for (int j = 0; j < 8; j++)
#pragma unroll
            for (int v = 0; v < 4; v++) acc[i][j][v] = 0.0f;

    auto issue = [&](int kt, int s) {
        int k0 = kt * 16;
        float* xd = xs + s * 3072;
        float* wd = ws + s * 3072;
#pragma unroll
        for (int j = 0; j < 2; j++) {
            int id = tid + j * 256;
            int r = id >> 2, c = id & 3;
            cpasync16(&xd[r * 24 + c * 4], &XP[(size_t)(rowBase + r) * DP + k0 + c * 4]);
            cpasync16(&wd[r * 24 + c * 4], &W[(size_t)(colBase + r) * DP + k0 + c * 4]);
        }
        CP_COMMIT;
    };

    issue(0, 0);
    issue(1, 1);

    for (int kt = 0; kt < KT; kt++) {
        int s = kt % 3;
        if (kt + 1 < KT) { CP_WAIT1; } else { CP_WAIT0; }
        __syncthreads();
        float* xb = xs + s * 3072;
        float* wb = ws + s * 3072;
#pragma unroll
        for (int kk = 0; kk < 2; kk++) {
            uint32_t a[2][4];
#pragma unroll
            for (int mt = 0; mt < 2; mt++) {
                int ar = (wm * 32 + mt * 16 + gp) * 24 + kk * 8 + tg * 2;
                float2 lo = *(float2*)&xb[ar];
                float2 hi = *(float2*)&xb[ar + 8 * 24];
                a[mt][0] = __float_as_uint(lo.x);
                a[mt][1] = __float_as_uint(hi.x);
                a[mt][2] = __float_as_uint(lo.y);
                a[mt][3] = __float_as_uint(hi.y);
            }
#pragma unroll
            for (int nt = 0; nt < 8; nt++) {
                int br = (wn * 64 + nt * 8 + gp) * 24 + kk * 8 + tg * 2;
                float2 bv = *(float2*)&wb[br];
                uint32_t b[2] = {__float_as_uint(bv.x), __float_as_uint(bv.y)};
#pragma unroll
                for (int mt = 0; mt < 2; mt++) mma_tf32(acc[mt][nt], a[mt], b);
            }
        }
        if (kt + 2 < KT) issue(kt + 2, (kt + 2) % 3);
        __syncthreads();
    }

#pragma unroll
    for (int mt = 0; mt < 2; mt++)
#pragma unroll
        for (int nt = 0; nt < 8; nt++) {
            int r0 = rowBase + wm * 32 + mt * 16 + gp;
            int col = colBase + wn * 64 + nt * 8 + 2 * tg;
            float bx = bias[col], by = bias[col + 1];
            int tt0 = r0 & 127, bb0 = r0 >> 7;
            *(float2*)&XG[((size_t)tt0 * B_SZ + bb0) * G + col] =
                make_float2(acc[mt][nt][0] + bx, acc[mt][nt][1] + by);
            int r1 = r0 + 8;
            int tt1 = r1 & 127, bb1 = r1 >> 7;
            *(float2*)&XG[((size_t)tt1 * B_SZ + bb1) * G + col] =
                make_float2(acc[mt][nt][2] + bx, acc[mt][nt][3] + by);
        }
}

__global__ __launch_bounds__(256) void proj_all_kernel() {
    extern __shared__ __align__(16) float psm[];
    float* xs = psm;            // 3 x 128x24
    float* ws = psm + 3 * 3072; // 3 x 128x24
    int bx = blockIdx.x;
    int rowBase = blockIdx.y * 128;
    if (bx < 8) {
        proj_impl(g_xp0, g_wih0, g_bias0, g_xg0, 304, 1024, 19, bx * 128, rowBase, xs, ws);
    } else if (bx < 10) {
        proj_impl(g_xp1, g_wih1, g_bias1, g_xg1, 80, 256, 5, (bx - 8) * 128, rowBase, xs, ws);
    } else {
        proj_impl(g_xp2, g_wih2, g_bias2, g_xg2, 48, 256, 3, (bx - 10) * 128, rowBase, xs, ws);
    }
}

// ---------------- launch 2: init h(0), c, barrier ----------------
__global__ void init_kernel() {
    int stride = gridDim.x * blockDim.x;
    int i0 = blockIdx.x * blockDim.x + threadIdx.x;
    if (i0 == 0) g_bar = 0;
    for (int i = i0; i < B_SZ * 256; i += stride) { g_h0[0][i] = 0.0f; g_c0[i] = 0.0f; }
    for (int i = i0; i < B_SZ * 64; i += stride) {
        g_h1[0][i] = 0.0f; g_c1[i] = 0.0f;
        g_h2[0][i] = 0.0f; g_c2[i] = 0.0f;
    }
}

// ---------------- launch 3: persistent recurrence ----------------
// blocks 0..127  : m0 (16 batch tiles x 32 rows) x (8 gate-col tiles x 128)
// blocks 128..135: m1 (8 batch tiles x 64 rows), full 256 gate cols
// blocks 136..143: m2 same
__global__ __launch_bounds__(256, 1) void persist_kernel() {
    extern __shared__ __align__(16) float sm[];
    int bid = blockIdx.x, tid = threadIdx.x;
    int lane = tid & 31, warp = tid >> 5;
    int gp = lane >> 2, tg = lane & 3;

    if (bid < 128) {
        // ================= module 0: H=256, G=1024 =================
        int bm = bid >> 3, bn = bid & 7;
        int rowBase = bm * 32, colBase = bn * 128;
        float* ws   = sm;                // 128 x 264
        float* hs   = sm + 128 * 264;    // 32 x 264 (reused as gates 32x128)
        float* xbuf = sm + 160 * 264;    // 32 x 128

        for (int idx = tid; idx < 128 * 64; idx += 256) {
            int r = idx >> 6, c = idx & 63;
            *(float4*)&ws[r * 264 + c * 4] =
                *(const float4*)&g_whh0[(colBase + r) * 256 + c * 4];
        }

        int wm = warp >> 2, wn = warp & 3; // 2m x 4n: 16-row x 32-col warp tile

        for (int t = 0; t < T_SZ; t++) {
            const float* hin = g_h0[t & 1];
            float* hout = g_h0[(t & 1) ^ 1];
            const float* xg = g_xg0 + (size_t)t * B_SZ * 1024;

            // prefetch this step's xg tile (32 rows x 128 cols)
#pragma unroll
            for (int j = 0; j < 4; j++) {
                int id = tid + j * 256;
                int r = id >> 5, c = id & 31;
                cpasync16(&xbuf[r * 128 + c * 4],
                          &xg[(size_t)(rowBase + r) * 1024 + colBase + c * 4]);
            }
            CP_COMMIT;

            for (int idx = tid; idx < 32 * 64; idx += 256) {
                int r = idx >> 6, c = idx & 63;
                float4 v = __ldcg((const float4*)&hin[(rowBase + r) * 256 + c * 4]);
                v.x = tf32r(v.x); v.y = tf32r(v.y); v.z = tf32r(v.z); v.w = tf32r(v.w);
                *(float4*)&hs[r * 264 + c * 4] = v;
            }
            __syncthreads();

            float acc[4][4];
#pragma unroll
            for (int j = 0; j < 4; j++)
#pragma unroll
                for (int v = 0; v < 4; v++) acc[j][v] = 0.0f;

#pragma unroll
            for (int kk = 0; kk < 32; kk++) {
                int ar = (wm * 16 + gp) * 264 + kk * 8 + tg * 2;
                float2 lo = *(float2*)&hs[ar];
                float2 hi = *(float2*)&hs[ar + 8 * 264];
                uint32_t a[4] = {__float_as_uint(lo.x), __float_as_uint(hi.x),
                                 __float_as_uint(lo.y), __float_as_uint(hi.y)};
#pragma unroll
                for (int nt = 0; nt < 4; nt++) {
                    int br = (wn * 32 + nt * 8 + gp) * 264 + kk * 8 + tg * 2;
                    float2 bv = *(float2*)&ws[br];
                    uint32_t b[2] = {__float_as_uint(bv.x), __float_as_uint(bv.y)};
                    mma_tf32(acc[nt], a, b);
                }
            }
            __syncthreads();

            float* gsm = hs; // 32 x 128
#pragma unroll
            for (int nt = 0; nt < 4; nt++) {
                int r = wm * 16 + gp, col = wn * 32 + nt * 8 + 2 * tg;
                *(float2*)&gsm[r * 128 + col] = make_float2(acc[nt][0], acc[nt][1]);
                *(float2*)&gsm[(r + 8) * 128 + col] = make_float2(acc[nt][2], acc[nt][3]);
            }
            CP_WAIT0;
            __syncthreads();

            for (int idx = tid; idx < 1024; idx += 256) {
                int kl = idx & 31, bl = idx >> 5;
                float4 gt = *(float4*)&gsm[bl * 128 + 4 * kl];
                int bg = rowBase + bl;
                int kg = bn * 32 + kl;
                float4 xv = *(float4*)&xbuf[bl * 128 + 4 * kl];
                float pi = gt.x + xv.x, pf = gt.y + xv.y, pg = gt.z + xv.z, po = gt.w + xv.w;
                float ii = sigm(pi), ff = sigm(pf), gg = tanhf(pg), oo = sigm(po);
                float cold = g_c0[bg * 256 + kg];
                float cn = ff * cold + ii * gg;
                float hn = oo * tanhf(cn);
                g_c0[bg * 256 + kg] = cn;
                __stcg(&hout[bg * 256 + swz(kg)], hn);
            }

            grid_bar(tid, (unsigned)(NBLK * (t + 1)));
        }
    } else {
        // ================= modules 1,2: H=64, G=256 =================
        int sub = bid - 128;
        int mod = sub >> 3, bm = sub & 7;
        int rowBase = bm * 64;
        const float* whh = mod ? g_whh2 : g_whh1;
        const float* xgb = mod ? g_xg2 : g_xg1;
        float* cb = mod ? g_c2 : g_c1;

        float* ws   = sm;                           // 256 x 72
        float* hs   = sm + 256 * 72;                // 64 x 72
        float* gsm  = sm + 256 * 72 + 64 * 72;      // 64 x 256
        float* xbuf = gsm + 64 * 256;               // 64 x 256

        for (int idx = tid; idx < 256 * 16; idx += 256) {
            int r = idx >> 4, c = idx & 15;
            *(float4*)&ws[r * 72 + c * 4] = *(const float4*)&whh[r * 64 + c * 4];
        }

        int wm = warp >> 2, wn = warp & 3; // 2m x 4n: 32-row x 64-col warp tile

        for (int t = 0; t < T_SZ; t++) {
            const float* hin = mod ? g_h2[t & 1] : g_h1[t & 1];
            float* hout = mod ? g_h2[(t & 1) ^ 1] : g_h1[(t & 1) ^ 1];
            const float* xg = xgb + (size_t)t * B_SZ * 256;

            // prefetch this step's xg tile (64 rows x 256 cols)
#pragma unroll
            for (int j = 0; j < 16; j++) {
                int id = tid + j * 256;
                int r = id >> 6, c = id & 63;
                cpasync16(&xbuf[r * 256 + c * 4],
                          &xg[(size_t)(rowBase + r) * 256 + c * 4]);
            }
            CP_COMMIT;

            for (int idx = tid; idx < 64 * 16; idx += 256) {
                int r = idx >> 4, c = idx & 15;
                float4 v = __ldcg((const float4*)&hin[(rowBase + r) * 64 + c * 4]);
                v.x = tf32r(v.x); v.y = tf32r(v.y); v.z = tf32r(v.z); v.w = tf32r(v.w);
                *(float4*)&hs[r * 72 + c * 4] = v;
            }
            __syncthreads();

            float acc[2][8][4];
#pragma unroll
            for (int i = 0; i < 2; i++)
#pragma unroll
                for (int j = 0; j < 8; j++)
#pragma unroll
                    for (int v = 0; v < 4; v++) acc[i][j][v] = 0.0f;

#pragma unroll
            for (int kk = 0; kk < 8; kk++) {
                uint32_t a[2][4];
#pragma unroll
                for (int mt = 0; mt < 2; mt++) {
                    int ar = (wm * 32 + mt * 16 + gp) * 72 + kk * 8 + tg * 2;
                    float2 lo = *(float2*)&hs[ar];
                    float2 hi = *(float2*)&hs[ar + 8 * 72];
                    a[mt][0] = __float_as_uint(lo.x);
                    a[mt][1] = __float_as_uint(hi.x);
                    a[mt][2] = __float_as_uint(lo.y);
                    a[mt][3] = __float_as_uint(hi.y);
                }
#pragma unroll
                for (int nt = 0; nt < 8; nt++) {
                    int br = (wn * 64 + nt * 8 + gp) * 72 + kk * 8 + tg * 2;
                    float2 bv = *(float2*)&ws[br];
                    uint32_t b[2] = {__float_as_uint(bv.x), __float_as_uint(bv.y)};
#pragma unroll
                    for (int mt = 0; mt < 2; mt++) mma_tf32(acc[mt][nt], a[mt], b);
                }
            }

#pragma unroll
            for (int mt = 0; mt < 2; mt++)
#pragma unroll
                for (int nt = 0; nt < 8; nt++) {
                    int r = wm * 32 + mt * 16 + gp;
                    int col = wn * 64 + nt * 8 + 2 * tg;
                    *(float2*)&gsm[r * 256 + col] = make_float2(acc[mt][nt][0], acc[mt][nt][1]);
                    *(float2*)&gsm[(r + 8) * 256 + col] = make_float2(acc[mt][nt][2], acc[mt][nt][3]);
                }
            CP_WAIT0;
            __syncthreads();

            for (int idx = tid; idx < 4096; idx += 256) {
                int kl = idx & 63, bl = idx >> 6;
                float4 gt = *(float4*)&gsm[bl * 256 + 4 * kl];
                int bg = rowBase + bl;
                float4 xv = *(float4*)&xbuf[bl * 256 + 4 * kl];
                float pi = gt.x + xv.x, pf = gt.y + xv.y, pg = gt.z + xv.z, po = gt.w + xv.w;
                float ii = sigm(pi), ff = sigm(pf), gg = tanhf(pg), oo = sigm(po);
                float cold = cb[bg * 64 + kl];
                float cn = ff * cold + ii * gg;
                float hn = oo * tanhf(cn);
                cb[bg * 64 + kl] = cn;
                __stcg(&hout[bg * 64 + swz(kl)], hn);
            }

            grid_bar(tid, (unsigned)(NBLK * (t + 1)));
        }
    }
}

// ---------------- launch 4: head ----------------
__global__ void head_kernel(const float* __restrict__ w1, const float* __restrict__ b1,
                            const float* __restrict__ w2, const float* __restrict__ b2,
                            float* __restrict__ out) {
    __shared__ float hc[8 * 384];
    __shared__ float red[256];
    int tid = threadIdx.x;
    int rowBase = blockIdx.x * 8;

    for (int i = tid; i < 8 * 384; i += 256) {
        int r = i / 384, d = i - r * 384;
        int bg = rowBase + r;
        float v;
        if (d < 256)      v = g_h0[0][bg * 256 + swz(d)];
        else if (d < 320) v = g_h1[0][bg * 64 + swz(d - 256)];
        else              v = g_h2[0][bg * 64 + swz(d - 320)];
        hc[i] = v;
    }
    __syncthreads();

    for (int pass = 0; pass < 2; pass++) {
        int row = pass * 4 + (tid >> 6);
        int cell = tid & 63;
        const float* wr = w1 + cell * 384;
        const float* hr = hc + row * 384;
        float a = b1[cell];
#pragma unroll 4
        for (int d = 0; d < 384; d++) a += hr[d] * wr[d];
        a = fmaxf(a, 0.0f);
        red[tid] = a * w2[cell];
        __syncthreads();
        if (cell == 0) {
            float s = 0.0f;
#pragma unroll
            for (int j = 0; j < 64; j++) s += red[tid + j];
            out[rowBase + row] = s + b2[0];
        }
        __syncthreads();
    }
}

// ---------------- launch ----------------
extern "C" void kernel_launch(void* const* d_in, const int* in_sizes, int n_in,
                              void* d_out, int out_size) {
    const float* x0    = (const float*)d_in[0];
    const float* x1    = (const float*)d_in[1];
    const float* x2    = (const float*)d_in[2];
    const float* w_ih0 = (const float*)d_in[3];
    const float* w_hh0 = (const float*)d_in[4];
    const float* b_ih0 = (const float*)d_in[5];
    const float* b_hh0 = (const float*)d_in[6];
    const float* w_ih1 = (const float*)d_in[7];
    const float* w_hh1 = (const float*)d_in[8];
    const float* b_ih1 = (const float*)d_in[9];
    const float* b_hh1 = (const float*)d_in[10];
    const float* w_ih2 = (const float*)d_in[11];
    const float* w_hh2 = (const float*)d_in[12];
    const float* b_ih2 = (const float*)d_in[13];
    const float* b_hh2 = (const float*)d_in[14];
    const float* w1    = (const float*)d_in[15];
    const float* b1    = (const float*)d_in[16];
    const float* w2    = (const float*)d_in[17];
    const float* b2    = (const float*)d_in[18];
    float* out = (float*)d_out;

    cudaFuncSetAttribute(persist_kernel, cudaFuncAttributeMaxDynamicSharedMemorySize,
                         SMEM_PERSIST);
    cudaFuncSetAttribute(proj_all_kernel, cudaFuncAttributeMaxDynamicSharedMemorySize,
                         SMEM_PROJ);

    // launch 0
    prep_all_kernel<<<1024, 256>>>(x0, x1, x2,
                                   w_ih0, w_hh0, b_ih0, b_hh0,
                                   w_ih1, w_hh1, b_ih1, b_hh1,
                                   w_ih2, w_hh2, b_ih2, b_hh2);
    // launch 1
    proj_all_kernel<<<dim3(12, 512), 256, SMEM_PROJ>>>();
    // launch 2
    init_kernel<<<256, 256>>>();
    // launch 3  (ncu captures this index)
    persist_kernel<<<NBLK, 256, SMEM_PERSIST>>>();
    // launch 4
    head_kernel<<<64, 256>>>(w1, b1, w2, b2, out);
}

// round 4
// speedup vs baseline: 2.4325x; 1.3617x over previous
#include <cuda_runtime.h>
#include <cstdint>

#define B_SZ 512
#define T_SZ 128
#define NBLK 144
#define SMEM_PERSIST 223232
#define SMEM_PROJ    73728

// ---------------- __device__ scratch (no allocations allowed) ----------------
__device__ __align__(128) float g_xg0[(size_t)T_SZ * B_SZ * 1024];
__device__ __align__(128) float g_xg1[(size_t)T_SZ * B_SZ * 256];
__device__ __align__(128) float g_xg2[(size_t)T_SZ * B_SZ * 256];
__device__ __align__(128) float g_xp0[(size_t)65536 * 304]; // K pair-swizzled
__device__ __align__(128) float g_xp1[(size_t)65536 * 80];
__device__ __align__(128) float g_xp2[(size_t)65536 * 48];
__device__ __align__(128) float g_wih0[1024 * 304];         // K pair-swizzled
__device__ __align__(128) float g_wih1[256 * 80];
__device__ __align__(128) float g_wih2[256 * 48];
__device__ __align__(128) float g_whh0[1024 * 256];         // K pair-swizzled
__device__ __align__(128) float g_whh1[256 * 64];
__device__ __align__(128) float g_whh2[256 * 64];
__device__ __align__(128) float g_bias0[1024];
__device__ __align__(128) float g_bias1[256];
__device__ __align__(128) float g_bias2[256];
__device__ __align__(128) float g_h0[2][B_SZ * 256];        // hidden pair-swizzled, tf32
__device__ __align__(128) float g_h1[2][B_SZ * 64];
__device__ __align__(128) float g_h2[2][B_SZ * 64];
__device__ __align__(128) float g_c1[B_SZ * 64];
__device__ __align__(128) float g_c2[B_SZ * 64];
__device__ __align__(128) unsigned g_bar0[16 * 32];         // one counter per bm group

// ---------------- helpers ----------------
__device__ __forceinline__ int swz(int k) {
    // within each 8-group: k -> pairs (k, k+4) adjacent
    return (k & ~7) | ((k & 3) << 1) | ((k >> 2) & 1);
}

__device__ __forceinline__ float tf32r(float x) {
    uint32_t u;
    asm("cvt.rna.tf32.f32 %0, %1;" : "=r"(u) : "f"(x));
    return __uint_as_float(u);
}

__device__ __forceinline__ void mma_tf32(float c[4], const uint32_t a[4], const uint32_t b[2]) {
    asm volatile(
        "mma.sync.aligned.m16n8k8.row.col.f32.tf32.tf32.f32 "
        "{%0,%1,%2,%3}, {%4,%5,%6,%7}, {%8,%9}, {%0,%1,%2,%3};"
        : "+f"(c[0]), "+f"(c[1]), "+f"(c[2]), "+f"(c[3])
        : "r"(a[0]), "r"(a[1]), "r"(a[2]), "r"(a[3]), "r"(b[0]), "r"(b[1]));
}

// fast, accurate-enough activations (ex2/rcp approx: rel err ~1e-7)
__device__ __forceinline__ float fex2(float x) {
    float r; asm("ex2.approx.f32 %0, %1;" : "=f"(r) : "f"(x)); return r;
}
__device__ __forceinline__ float frcp(float x) {
    float r; asm("rcp.approx.f32 %0, %1;" : "=f"(r) : "f"(x)); return r;
}
__device__ __forceinline__ float sigm(float x) {
    return frcp(1.0f + fex2(-1.4426950408889634f * x));
}
__device__ __forceinline__ float tanhfast(float x) {
    return 2.0f * frcp(1.0f + fex2(-2.8853900817779268f * x)) - 1.0f;
}

__device__ __forceinline__ void cpasync16(void* dst, const void* src) {
    uint32_t d = (uint32_t)__cvta_generic_to_shared(dst);
    asm volatile("cp.async.ca.shared.global [%0], [%1], 16;" :: "r"(d), "l"(src));
}
// cg (L2-only) — REQUIRED for h ping-pong (peer-SM writes; .ca would hit stale L1)
__device__ __forceinline__ void cpasync16cg(void* dst, const void* src) {
    uint32_t d = (uint32_t)__cvta_generic_to_shared(dst);
    asm volatile("cp.async.cg.shared.global [%0], [%1], 16;" :: "r"(d), "l"(src));
}
#define CP_COMMIT asm volatile("cp.async.commit_group;")
#define CP_WAIT1  asm volatile("cp.async.wait_group 1;")
#define CP_WAIT0  asm volatile("cp.async.wait_group 0;")

// ---------------- launch 0: prep weights (gate-interleave + K-swizzle + tf32) + pad x ----
__global__ void prep_all_kernel(
    const float* __restrict__ x0, const float* __restrict__ x1, const float* __restrict__ x2,
    const float* __restrict__ wih0, const float* __restrict__ whh0,
    const float* __restrict__ bih0, const float* __restrict__ bhh0,
    const float* __restrict__ wih1, const float* __restrict__ whh1,
    const float* __restrict__ bih1, const float* __restrict__ bhh1,
    const float* __restrict__ wih2, const float* __restrict__ whh2,
    const float* __restrict__ bih2, const float* __restrict__ bhh2)
{
    size_t stride = (size_t)gridDim.x * blockDim.x;
    size_t t0 = (size_t)blockIdx.x * blockDim.x + threadIdx.x;

    for (size_t i = t0; i < (size_t)65536 * 304; i += stride) {
        int r = (int)(i / 304), d = (int)(i - (size_t)r * 304);
        g_xp0[(size_t)r * 304 + swz(d)] = (d < 300) ? tf32r(x0[(size_t)r * 300 + d]) : 0.0f;
    }
    for (size_t i = t0; i < (size_t)65536 * 80; i += stride) {
        int r = (int)(i / 80), d = (int)(i - (size_t)r * 80);
        g_xp1[(size_t)r * 80 + swz(d)] = (d < 74) ? tf32r(x1[(size_t)r * 74 + d]) : 0.0f;
    }
    for (size_t i = t0; i < (size_t)65536 * 48; i += stride) {
        int r = (int)(i / 48), d = (int)(i - (size_t)r * 48);
        g_xp2[(size_t)r * 48 + swz(d)] = (d < 35) ? tf32r(x2[(size_t)r * 35 + d]) : 0.0f;
    }

    for (size_t ii = t0; ii < 1024 * 304; ii += stride) {
        int i = (int)ii;
        int gp = i / 304, dp = i - gp * 304;
        int k = gp >> 2, q = gp & 3, go = q * 256 + k;
        g_wih0[gp * 304 + swz(dp)] = (dp < 300) ? tf32r(wih0[go * 300 + dp]) : 0.0f;
    }
    for (size_t ii = t0; ii < 256 * 80; ii += stride) {
        int i = (int)ii;
        int gp = i / 80, dp = i - gp * 80;
        int k = gp >> 2, q = gp & 3, go = q * 64 + k;
        g_wih1[gp * 80 + swz(dp)] = (dp < 74) ? tf32r(wih1[go * 74 + dp]) : 0.0f;
    }
    for (size_t ii = t0; ii < 256 * 48; ii += stride) {
        int i = (int)ii;
        int gp = i / 48, dp = i - gp * 48;
        int k = gp >> 2, q = gp & 3, go = q * 64 + k;
        g_wih2[gp * 48 + swz(dp)] = (dp < 35) ? tf32r(wih2[go * 35 + dp]) : 0.0f;
    }
    for (size_t ii = t0; ii < 1024 * 256; ii += stride) {
        int i = (int)ii;
        int gp = i >> 8, dp = i & 255;
        int k = gp >> 2, q = gp & 3, go = q * 256 + k;
        g_whh0[gp * 256 + swz(dp)] = tf32r(whh0[go * 256 + dp]);
    }
    for (size_t ii = t0; ii < 256 * 64; ii += stride) {
        int i = (int)ii;
        int gp = i >> 6, dp = i & 63;
        int k = gp >> 2, q = gp & 3, go = q * 64 + k;
        g_whh1[gp * 64 + swz(dp)] = tf32r(whh1[go * 64 + dp]);
        g_whh2[gp * 64 + swz(dp)] = tf32r(whh2[go * 64 + dp]);
    }
    for (size_t ii = t0; ii < 1024; ii += stride) {
        int i = (int)ii;
        int k = i >> 2, q = i & 3, go = q * 256 + k;
        g_bias0[i] = bih0[go] + bhh0[go];
    }
    for (size_t ii = t0; ii < 256; ii += stride) {
        int i = (int)ii;
        int k = i >> 2, q = i & 3, go = q * 64 + k;
        g_bias1[i] = bih1[go] + bhh1[go];
        g_bias2[i] = bih2[go] + bhh2[go];
    }
}

// ---------------- launch 1: all input projections, 128x128 tiles, 3-stage cp.async ------
__device__ __forceinline__ void proj_impl(
    const float* __restrict__ XP, const float* __restrict__ W,
    const float* __restrict__ bias, float* __restrict__ XG,
    int DP, int G, int KT, int colBase, int rowBase, float* xs, float* ws)
{
    int tid = threadIdx.x, lane = tid & 31, warp = tid >> 5;
    int gp = lane >> 2, tg = lane & 3;
    int wm = warp >> 1, wn = warp & 1; // 4m x 2n warps

    float acc[2][8][4];
#pragma unroll
    for (int i = 0; i < 2; i++)
#pragma unroll
        for (int j = 0; j < 8; j++)
#pragma unroll
            for (int v = 0; v < 4; v++) acc[i][j][v] = 0.0f;

    auto issue = [&](int kt, int s) {
        int k0 = kt * 16;
        float* xd = xs + s * 3072;
        float* wd = ws + s * 3072;
#pragma unroll
        for (int j = 0; j < 2; j++) {
            int id = tid + j * 256;
            int r = id >> 2, c = id & 3;
            cpasync16(&xd[r * 24 + c * 4], &XP[(size_t)(rowBase + r) * DP + k0 + c * 4]);
            cpasync16(&wd[r * 24 + c * 4], &W[(size_t)(colBase + r) * DP + k0 + c * 4]);
        }
        CP_COMMIT;
    };

    issue(0, 0);
    issue(1, 1);

    for (int kt = 0; kt < KT; kt++) {
        int s = kt % 3;
        if (kt + 1 < KT) { CP_WAIT1; } else { CP_WAIT0; }
        __syncthreads();
        float* xb = xs + s * 3072;
        float* wb = ws + s * 3072;
#pragma unroll
        for (int kk = 0; kk < 2; kk++) {
            uint32_t a[2][4];
#pragma unroll
            for (int mt = 0; mt < 2; mt++) {
                int ar = (wm * 32 + mt * 16 + gp) * 24 + kk * 8 + tg * 2;
                float2 lo = *(float2*)&xb[ar];
                float2 hi = *(float2*)&xb[ar + 8 * 24];
                a[mt][0] = __float_as_uint(lo.x);
                a[mt][1] = __float_as_uint(hi.x);
                a[mt][2] = __float_as_uint(lo.y);
                a[mt][3] = __float_as_uint(hi.y);
            }
#pragma unroll
            for (int nt = 0; nt < 8; nt++) {
                int br = (wn * 64 + nt * 8 + gp) * 24 + kk * 8 + tg * 2;
                float2 bv = *(float2*)&wb[br];
                uint32_t b[2] = {__float_as_uint(bv.x), __float_as_uint(bv.y)};
#pragma unroll
                for (int mt = 0; mt < 2; mt++) mma_tf32(acc[mt][nt], a[mt], b);
            }
        }
        if (kt + 2 < KT) issue(kt + 2, (kt + 2) % 3);
        __syncthreads();
    }

#pragma unroll
    for (int mt = 0; mt < 2; mt++)
#pragma unroll
        for (int nt = 0; nt < 8; nt++) {
            int r0 = rowBase + wm * 32 + mt * 16 + gp;
            int col = colBase + wn * 64 + nt * 8 + 2 * tg;
            float bx = bias[col], by = bias[col + 1];
            int tt0 = r0 & 127, bb0 = r0 >> 7;
            *(float2*)&XG[((size_t)tt0 * B_SZ + bb0) * G + col] =
                make_float2(acc[mt][nt][0] + bx, acc[mt][nt][1] + by);
            int r1 = r0 + 8;
            int tt1 = r1 & 127, bb1 = r1 >> 7;
            *(float2*)&XG[((size_t)tt1 * B_SZ + bb1) * G + col] =
                make_float2(acc[mt][nt][2] + bx, acc[mt][nt][3] + by);
        }
}

__global__ __launch_bounds__(256) void proj_all_kernel() {
    extern __shared__ __align__(16) float psm[];
    float* xs = psm;
    float* ws = psm + 3 * 3072;
    int bx = blockIdx.x;
    int rowBase = blockIdx.y * 128;
    if (bx < 8) {
        proj_impl(g_xp0, g_wih0, g_bias0, g_xg0, 304, 1024, 19, bx * 128, rowBase, xs, ws);
    } else if (bx < 10) {
        proj_impl(g_xp1, g_wih1, g_bias1, g_xg1, 80, 256, 5, (bx - 8) * 128, rowBase, xs, ws);
    } else {
        proj_impl(g_xp2, g_wih2, g_bias2, g_xg2, 48, 256, 3, (bx - 10) * 128, rowBase, xs, ws);
    }
}

// ---------------- launch 2: init ----------------
__global__ void init_kernel() {
    int stride = gridDim.x * blockDim.x;
    int i0 = blockIdx.x * blockDim.x + threadIdx.x;
    for (int i = i0; i < 16 * 32; i += stride) g_bar0[i] = 0u;
    for (int i = i0; i < B_SZ * 256; i += stride) g_h0[0][i] = 0.0f;
    for (int i = i0; i < B_SZ * 64; i += stride) {
        g_h1[0][i] = 0.0f; g_c1[i] = 0.0f;
        g_h2[0][i] = 0.0f; g_c2[i] = 0.0f;
    }
}

// ---------------- launch 3: persistent recurrence ----------------
// blocks 0..127  : m0, block = 32 batch rows x 128 gate cols; per-bm 8-block barrier
// blocks 128..143: m1/m2, block = 64 batch rows x all 256 gate cols; fully independent
__global__ __launch_bounds__(256, 1) void persist_kernel() {
    extern __shared__ __align__(16) float sm[];
    int bid = blockIdx.x, tid = threadIdx.x;
    int lane = tid & 31, warp = tid >> 5;
    int gp = lane >> 2, tg = lane & 3;

    if (bid < 128) {
        // ================= module 0: H=256, G=1024 =================
        int bm = bid >> 3, bn = bid & 7;
        int rowBase = bm * 32, colBase = bn * 128;
        float* hs   = sm;                  // 32 x 264
        float* xbuf = sm + 8448;           // 32 x 128
        float* gsm  = sm + 8448 + 4096;    // 32 x 128

        // weights resident in registers: warp owns cols [wn*16, wn*16+16), all K
        int wn = warp;
        uint32_t breg[32][2][2];
#pragma unroll
        for (int kk = 0; kk < 32; kk++)
#pragma unroll
            for (int nt = 0; nt < 2; nt++) {
                float2 v = *(const float2*)
                    &g_whh0[(size_t)(colBase + wn * 16 + nt * 8 + gp) * 256 + kk * 8 + tg * 2];
                breg[kk][nt][0] = __float_as_uint(v.x);
                breg[kk][nt][1] = __float_as_uint(v.y);
            }

        // cell state in registers
        float creg[4] = {0.0f, 0.0f, 0.0f, 0.0f};

        unsigned* cnt = &g_bar0[bm * 32];

        for (int t = 0; t < T_SZ; t++) {
            const float* hin = g_h0[t & 1];
            float* hout = g_h0[(t & 1) ^ 1];
            const float* xg = g_xg0 + (size_t)t * B_SZ * 1024;

            // stage xg tile (ca ok: written once by proj) and h tile (cg REQUIRED)
#pragma unroll
            for (int j = 0; j < 4; j++) {
                int id = tid + j * 256;
                int r = id >> 5, c = id & 31;
                cpasync16(&xbuf[r * 128 + c * 4],
                          &xg[(size_t)(rowBase + r) * 1024 + colBase + c * 4]);
            }
#pragma unroll
            for (int j = 0; j < 8; j++) {
                int id = tid + j * 256;
                int r = id >> 6, c = id & 63;
                cpasync16cg(&hs[r * 264 + c * 4], &hin[(rowBase + r) * 256 + c * 4]);
            }
            CP_COMMIT;
            CP_WAIT0;
            __syncthreads();

            float acc[2][2][4];
#pragma unroll
            for (int i = 0; i < 2; i++)
#pragma unroll
                for (int j = 0; j < 2; j++)
#pragma unroll
                    for (int v = 0; v < 4; v++) acc[i][j][v] = 0.0f;

#pragma unroll
            for (int kk = 0; kk < 32; kk++) {
                int kb = kk * 8 + tg * 2;
                float2 lo0 = *(float2*)&hs[gp * 264 + kb];
                float2 hi0 = *(float2*)&hs[(gp + 8) * 264 + kb];
                float2 lo1 = *(float2*)&hs[(gp + 16) * 264 + kb];
                float2 hi1 = *(float2*)&hs[(gp + 24) * 264 + kb];
                uint32_t a0[4] = {__float_as_uint(lo0.x), __float_as_uint(hi0.x),
                                  __float_as_uint(lo0.y), __float_as_uint(hi0.y)};
                uint32_t a1[4] = {__float_as_uint(lo1.x), __float_as_uint(hi1.x),
                                  __float_as_uint(lo1.y), __float_as_uint(hi1.y)};
                mma_tf32(acc[0][0], a0, breg[kk][0]);
                mma_tf32(acc[0][1], a0, breg[kk][1]);
                mma_tf32(acc[1][0], a1, breg[kk][0]);
                mma_tf32(acc[1][1], a1, breg[kk][1]);
            }

#pragma unroll
            for (int mt = 0; mt < 2; mt++)
#pragma unroll
                for (int nt = 0; nt < 2; nt++) {
                    int r = mt * 16 + gp, col = wn * 16 + nt * 8 + tg * 2;
                    *(float2*)&gsm[r * 128 + col] =
                        make_float2(acc[mt][nt][0], acc[mt][nt][1]);
                    *(float2*)&gsm[(r + 8) * 128 + col] =
                        make_float2(acc[mt][nt][2], acc[mt][nt][3]);
                }
            __syncthreads();

            // cell update: c lives in creg[j] with fixed (row, cell) per thread
#pragma unroll
            for (int j = 0; j < 4; j++) {
                int idx = tid + j * 256;
                int bl = idx >> 5, kl = idx & 31;
                float4 gt = *(float4*)&gsm[bl * 128 + 4 * kl];
                float4 xv = *(float4*)&xbuf[bl * 128 + 4 * kl];
                float ii = sigm(gt.x + xv.x);
                float ff = sigm(gt.y + xv.y);
                float gg = tanhfast(gt.z + xv.z);
                float oo = sigm(gt.w + xv.w);
                float cn = ff * creg[j] + ii * gg;
                creg[j] = cn;
                float hn = oo * tanhfast(cn);
                hout[(rowBase + bl) * 256 + swz(bn * 32 + kl)] = tf32r(hn);
            }

            // 8-block group barrier (per bm)
            __syncthreads();
            if (tid == 0) {
                __threadfence();
                atomicAdd(cnt, 1u);
                unsigned tgt = 8u * (unsigned)(t + 1);
                while (*(volatile unsigned*)cnt < tgt) {}
                __threadfence();
            }
            __syncthreads();
        }
    } else {
        // ================= modules 1,2: H=64, G=256, fully independent ============
        int sub = bid - 128;
        int mod = sub >> 3, bm = sub & 7;
        int rowBase = bm * 64;
        const float* whh = mod ? g_whh2 : g_whh1;
        const float* xgb = mod ? g_xg2 : g_xg1;
        float* cb = mod ? g_c2 : g_c1;

        float* ws   = sm;                           // 256 x 72
        float* hs   = sm + 256 * 72;                // 64 x 72
        float* gsm  = sm + 256 * 72 + 64 * 72;      // 64 x 256
        float* xbuf = gsm + 64 * 256;               // 64 x 256

        for (int idx = tid; idx < 256 * 16; idx += 256) {
            int r = idx >> 4, c = idx & 15;
            *(float4*)&ws[r * 72 + c * 4] = *(const float4*)&whh[r * 64 + c * 4];
        }

        int wm = warp >> 2, wn = warp & 3; // 2m x 4n: 32-row x 64-col warp tile

        for (int t = 0; t < T_SZ; t++) {
            const float* hin = mod ? g_h2[t & 1] : g_h1[t & 1];
            float* hout = mod ? g_h2[(t & 1) ^ 1] : g_h1[(t & 1) ^ 1];
            const float* xg = xgb + (size_t)t * B_SZ * 256;

#pragma unroll
            for (int j = 0; j < 16; j++) {
                int id = tid + j * 256;
                int r = id >> 6, c = id & 63;
                cpasync16(&xbuf[r * 256 + c * 4],
                          &xg[(size_t)(rowBase + r) * 256 + c * 4]);
            }
#pragma unroll
            for (int j = 0; j < 4; j++) {
                int id = tid + j * 256;
                int r = id >> 4, c = id & 15;
                cpasync16cg(&hs[r * 72 + c * 4], &hin[(rowBase + r) * 64 + c * 4]);
            }
            CP_COMMIT;
            CP_WAIT0;
            __syncthreads();

            float acc[2][8][4];
#pragma unroll
            for (int i = 0; i < 2; i++)
#pragma unroll
                for (int j = 0; j < 8; j++)
#pragma unroll
                    for (int v = 0; v < 4; v++) acc[i][j][v] = 0.0f;

#pragma unroll
            for (int kk = 0; kk < 8; kk++) {
                uint32_t a[2][4];
#pragma unroll
                for (int mt = 0; mt < 2; mt++) {
                    int ar = (wm * 32 + mt * 16 + gp) * 72 + kk * 8 + tg * 2;
                    float2 lo = *(float2*)&hs[ar];
                    float2 hi = *(float2*)&hs[ar + 8 * 72];
                    a[mt][0] = __float_as_uint(lo.x);
                    a[mt][1] = __float_as_uint(hi.x);
                    a[mt][2] = __float_as_uint(lo.y);
                    a[mt][3] = __float_as_uint(hi.y);
                }
#pragma unroll
                for (int nt = 0; nt < 8; nt++) {
                    int br = (wn * 64 + nt * 8 + gp) * 72 + kk * 8 + tg * 2;
                    float2 bv = *(float2*)&ws[br];
                    uint32_t b[2] = {__float_as_uint(bv.x), __float_as_uint(bv.y)};
#pragma unroll
                    for (int mt = 0; mt < 2; mt++) mma_tf32(acc[mt][nt], a[mt], b);
                }
            }

#pragma unroll
            for (int mt = 0; mt < 2; mt++)
#pragma unroll
                for (int nt = 0; nt < 8; nt++) {
                    int r = wm * 32 + mt * 16 + gp;
                    int col = wn * 64 + nt * 8 + 2 * tg;
                    *(float2*)&gsm[r * 256 + col] = make_float2(acc[mt][nt][0], acc[mt][nt][1]);
                    *(float2*)&gsm[(r + 8) * 256 + col] = make_float2(acc[mt][nt][2], acc[mt][nt][3]);
                }
            __syncthreads();

            for (int idx = tid; idx < 4096; idx += 256) {
                int kl = idx & 63, bl = idx >> 6;
                float4 gt = *(float4*)&gsm[bl * 256 + 4 * kl];
                int bg = rowBase + bl;
                float4 xv = *(float4*)&xbuf[bl * 256 + 4 * kl];
                float ii = sigm(gt.x + xv.x);
                float ff = sigm(gt.y + xv.y);
                float gg = tanhfast(gt.z + xv.z);
                float oo = sigm(gt.w + xv.w);
                float cold = cb[bg * 64 + kl];
                float cn = ff * cold + ii * gg;
                float hn = oo * tanhfast(cn);
                cb[bg * 64 + kl] = cn;
                hout[bg * 64 + swz(kl)] = tf32r(hn);
            }
            __syncthreads();
        }
    }
}

// ---------------- launch 4: head ----------------
__global__ void head_kernel(const float* __restrict__ w1, const float* __restrict__ b1,
                            const float* __restrict__ w2, const float* __restrict__ b2,
                            float* __restrict__ out) {
    __shared__ float hc[8 * 384];
    __shared__ float red[256];
    int tid = threadIdx.x;
    int rowBase = blockIdx.x * 8;

    for (int i = tid; i < 8 * 384; i += 256) {
        int r = i / 384, d = i - r * 384;
        int bg = rowBase + r;
        float v;
        if (d < 256)      v = g_h0[0][bg * 256 + swz(d)];
        else if (d < 320) v = g_h1[0][bg * 64 + swz(d - 256)];
        else              v = g_h2[0][bg * 64 + swz(d - 320)];
        hc[i] = v;
    }
    __syncthreads();

    for (int pass = 0; pass < 2; pass++) {
        int row = pass * 4 + (tid >> 6);
        int cell = tid & 63;
        const float* wr = w1 + cell * 384;
        const float* hr = hc + row * 384;
        float a = b1[cell];
#pragma unroll 4
        for (int d = 0; d < 384; d++) a += hr[d] * wr[d];
        a = fmaxf(a, 0.0f);
        red[tid] = a * w2[cell];
        __syncthreads();
        if (cell == 0) {
            float s = 0.0f;
#pragma unroll
            for (int j = 0; j < 64; j++) s += red[tid + j];
            out[rowBase + row] = s + b2[0];
        }
        __syncthreads();
    }
}

// ---------------- launch ----------------
extern "C" void kernel_launch(void* const* d_in, const int* in_sizes, int n_in,
                              void* d_out, int out_size) {
    const float* x0    = (const float*)d_in[0];
    const float* x1    = (const float*)d_in[1];
    const float* x2    = (const float*)d_in[2];
    const float* w_ih0 = (const float*)d_in[3];
    const float* w_hh0 = (const float*)d_in[4];
    const float* b_ih0 = (const float*)d_in[5];
    const float* b_hh0 = (const float*)d_in[6];
    const float* w_ih1 = (const float*)d_in[7];
    const float* w_hh1 = (const float*)d_in[8];
    const float* b_ih1 = (const float*)d_in[9];
    const float* b_hh1 = (const float*)d_in[10];
    const float* w_ih2 = (const float*)d_in[11];
    const float* w_hh2 = (const float*)d_in[12];
    const float* b_ih2 = (const float*)d_in[13];
    const float* b_hh2 = (const float*)d_in[14];
    const float* w1    = (const float*)d_in[15];
    const float* b1    = (const float*)d_in[16];
    const float* w2    = (const float*)d_in[17];
    const float* b2    = (const float*)d_in[18];
    float* out = (float*)d_out;

    cudaFuncSetAttribute(persist_kernel, cudaFuncAttributeMaxDynamicSharedMemorySize,
                         SMEM_PERSIST);
    cudaFuncSetAttribute(proj_all_kernel, cudaFuncAttributeMaxDynamicSharedMemorySize,
                         SMEM_PROJ);

    // launch 0
    prep_all_kernel<<<1024, 256>>>(x0, x1, x2,
                                   w_ih0, w_hh0, b_ih0, b_hh0,
                                   w_ih1, w_hh1, b_ih1, b_hh1,
                                   w_ih2, w_hh2, b_ih2, b_hh2);
    // launch 1
    proj_all_kernel<<<dim3(12, 512), 256, SMEM_PROJ>>>();
    // launch 2
    init_kernel<<<256, 256>>>();
    // launch 3  (ncu capture index)
    persist_kernel<<<NBLK, 256, SMEM_PERSIST>>>();
    // launch 4
    head_kernel<<<64, 256>>>(w1, b1, w2, b2, out);
}

// round 5
// speedup vs baseline: 2.5192x; 1.0356x over previous
#include <cuda_runtime.h>
#include <cstdint>

#define B_SZ 512
#define T_SZ 128
#define NBLK 144
#define SMEM_PERSIST 223232
#define SMEM_PROJ    110592

// ---------------- __device__ scratch (no allocations allowed) ----------------
__device__ __align__(128) float g_xg0[(size_t)T_SZ * B_SZ * 1024];
__device__ __align__(128) float g_xg1[(size_t)T_SZ * B_SZ * 256];
__device__ __align__(128) float g_xg2[(size_t)T_SZ * B_SZ * 256];
__device__ __align__(128) float g_xp0[(size_t)65536 * 304]; // K pair-swizzled
__device__ __align__(128) float g_xp1[(size_t)65536 * 80];
__device__ __align__(128) float g_xp2[(size_t)65536 * 48];
__device__ __align__(128) float g_wih0[1024 * 304];         // K pair-swizzled
__device__ __align__(128) float g_wih1[256 * 80];
__device__ __align__(128) float g_wih2[256 * 48];
__device__ __align__(128) float g_whh0[1024 * 256];         // K pair-swizzled
__device__ __align__(128) float g_whh1[256 * 64];
__device__ __align__(128) float g_whh2[256 * 64];
__device__ __align__(128) float g_bias0[1024];
__device__ __align__(128) float g_bias1[256];
__device__ __align__(128) float g_bias2[256];
__device__ __align__(128) float g_h0[2][B_SZ * 256];        // hidden pair-swizzled, tf32
__device__ __align__(128) float g_h1[2][B_SZ * 64];
__device__ __align__(128) float g_h2[2][B_SZ * 64];
__device__ __align__(128) float g_c1[B_SZ * 64];
__device__ __align__(128) float g_c2[B_SZ * 64];
__device__ __align__(128) unsigned g_bar0[16 * 32];         // one counter per bm group

// ---------------- helpers ----------------
__device__ __forceinline__ int swz(int k) {
    return (k & ~7) | ((k & 3) << 1) | ((k >> 2) & 1);
}

__device__ __forceinline__ float tf32r(float x) {
    uint32_t u;
    asm("cvt.rna.tf32.f32 %0, %1;" : "=r"(u) : "f"(x));
    return __uint_as_float(u);
}

__device__ __forceinline__ void mma_tf32(float c[4], const uint32_t a[4], const uint32_t b[2]) {
    asm volatile(
        "mma.sync.aligned.m16n8k8.row.col.f32.tf32.tf32.f32 "
        "{%0,%1,%2,%3}, {%4,%5,%6,%7}, {%8,%9}, {%0,%1,%2,%3};"
        : "+f"(c[0]), "+f"(c[1]), "+f"(c[2]), "+f"(c[3])
        : "r"(a[0]), "r"(a[1]), "r"(a[2]), "r"(a[3]), "r"(b[0]), "r"(b[1]));
}

__device__ __forceinline__ float fex2(float x) {
    float r; asm("ex2.approx.f32 %0, %1;" : "=f"(r) : "f"(x)); return r;
}
__device__ __forceinline__ float frcp(float x) {
    float r; asm("rcp.approx.f32 %0, %1;" : "=f"(r) : "f"(x)); return r;
}
__device__ __forceinline__ float sigm(float x) {
    return frcp(1.0f + fex2(-1.4426950408889634f * x));
}
__device__ __forceinline__ float tanhfast(float x) {
    return 2.0f * frcp(1.0f + fex2(-2.8853900817779268f * x)) - 1.0f;
}

__device__ __forceinline__ void cpasync16(void* dst, const void* src) {
    uint32_t d = (uint32_t)__cvta_generic_to_shared(dst);
    asm volatile("cp.async.ca.shared.global [%0], [%1], 16;" :: "r"(d), "l"(src));
}
// cg (L2-only) — REQUIRED for h ping-pong (peer-SM writes; .ca would hit stale L1)
__device__ __forceinline__ void cpasync16cg(void* dst, const void* src) {
    uint32_t d = (uint32_t)__cvta_generic_to_shared(dst);
    asm volatile("cp.async.cg.shared.global [%0], [%1], 16;" :: "r"(d), "l"(src));
}
#define CP_COMMIT asm volatile("cp.async.commit_group;")
#define CP_WAIT1  asm volatile("cp.async.wait_group 1;")
#define CP_WAIT0  asm volatile("cp.async.wait_group 0;")

// ---------------- launch 0: prep weights (gate-interleave + K-swizzle + tf32) ----------
__global__ void prep_w_kernel(
    const float* __restrict__ wih0, const float* __restrict__ whh0,
    const float* __restrict__ bih0, const float* __restrict__ bhh0,
    const float* __restrict__ wih1, const float* __restrict__ whh1,
    const float* __restrict__ bih1, const float* __restrict__ bhh1,
    const float* __restrict__ wih2, const float* __restrict__ whh2,
    const float* __restrict__ bih2, const float* __restrict__ bhh2)
{
    size_t stride = (size_t)gridDim.x * blockDim.x;
    size_t t0 = (size_t)blockIdx.x * blockDim.x + threadIdx.x;

    for (size_t ii = t0; ii < 1024 * 304; ii += stride) {
        int i = (int)ii;
        int gp = i / 304, dp = i - gp * 304;
        int k = gp >> 2, q = gp & 3, go = q * 256 + k;
        g_wih0[gp * 304 + swz(dp)] = (dp < 300) ? tf32r(wih0[go * 300 + dp]) : 0.0f;
    }
    for (size_t ii = t0; ii < 256 * 80; ii += stride) {
        int i = (int)ii;
        int gp = i / 80, dp = i - gp * 80;
        int k = gp >> 2, q = gp & 3, go = q * 64 + k;
        g_wih1[gp * 80 + swz(dp)] = (dp < 74) ? tf32r(wih1[go * 74 + dp]) : 0.0f;
    }
    for (size_t ii = t0; ii < 256 * 48; ii += stride) {
        int i = (int)ii;
        int gp = i / 48, dp = i - gp * 48;
        int k = gp >> 2, q = gp & 3, go = q * 64 + k;
        g_wih2[gp * 48 + swz(dp)] = (dp < 35) ? tf32r(wih2[go * 35 + dp]) : 0.0f;
    }
    for (size_t ii = t0; ii < 1024 * 256; ii += stride) {
        int i = (int)ii;
        int gp = i >> 8, dp = i & 255;
        int k = gp >> 2, q = gp & 3, go = q * 256 + k;
        g_whh0[gp * 256 + swz(dp)] = tf32r(whh0[go * 256 + dp]);
    }
    for (size_t ii = t0; ii < 256 * 64; ii += stride) {
        int i = (int)ii;
        int gp = i >> 6, dp = i & 63;
        int k = gp >> 2, q = gp & 3, go = q * 64 + k;
        g_whh1[gp * 64 + swz(dp)] = tf32r(whh1[go * 64 + dp]);
        g_whh2[gp * 64 + swz(dp)] = tf32r(whh2[go * 64 + dp]);
    }
    for (size_t ii = t0; ii < 1024; ii += stride) {
        int i = (int)ii;
        int k = i >> 2, q = i & 3, go = q * 256 + k;
        g_bias0[i] = bih0[go] + bhh0[go];
    }
    for (size_t ii = t0; ii < 256; ii += stride) {
        int i = (int)ii;
        int k = i >> 2, q = i & 3, go = q * 64 + k;
        g_bias1[i] = bih1[go] + bhh1[go];
        g_bias2[i] = bih2[go] + bhh2[go];
    }
}

// ---------------- launch 1: pad x -> xp (tf32 + K pair-swizzle) ----------------
__global__ void prep_x_kernel(
    const float* __restrict__ x0, const float* __restrict__ x1, const float* __restrict__ x2)
{
    size_t stride = (size_t)gridDim.x * blockDim.x;
    size_t t0 = (size_t)blockIdx.x * blockDim.x + threadIdx.x;

    for (size_t i = t0; i < (size_t)65536 * 304; i += stride) {
        int r = (int)(i / 304), d = (int)(i - (size_t)r * 304);
        g_xp0[(size_t)r * 304 + swz(d)] = (d < 300) ? tf32r(x0[(size_t)r * 300 + d]) : 0.0f;
    }
    for (size_t i = t0; i < (size_t)65536 * 80; i += stride) {
        int r = (int)(i / 80), d = (int)(i - (size_t)r * 80);
        g_xp1[(size_t)r * 80 + swz(d)] = (d < 74) ? tf32r(x1[(size_t)r * 74 + d]) : 0.0f;
    }
    for (size_t i = t0; i < (size_t)65536 * 48; i += stride) {
        int r = (int)(i / 48), d = (int)(i - (size_t)r * 48);
        g_xp2[(size_t)r * 48 + swz(d)] = (d < 35) ? tf32r(x2[(size_t)r * 35 + d]) : 0.0f;
    }
}

// ---------------- launch 2: init ----------------
__global__ void init_kernel() {
    int stride = gridDim.x * blockDim.x;
    int i0 = blockIdx.x * blockDim.x + threadIdx.x;
    for (int i = i0; i < 16 * 32; i += stride) g_bar0[i] = 0u;
    for (int i = i0; i < B_SZ * 256; i += stride) g_h0[0][i] = 0.0f;
    for (int i = i0; i < B_SZ * 64; i += stride) {
        g_h1[0][i] = 0.0f; g_c1[i] = 0.0f;
        g_h2[0][i] = 0.0f; g_c2[i] = 0.0f;
    }
}

// ---------------- launch 3: all input projections, 128x256 tiles, 3-stage cp.async ------
__device__ __forceinline__ void proj_impl(
    const float* __restrict__ XP, const float* __restrict__ W,
    const float* __restrict__ bias, float* __restrict__ XG,
    int DP, int G, int KT, int colBase, int rowBase, float* xs, float* ws)
{
    int tid = threadIdx.x, lane = tid & 31, warp = tid >> 5;
    int gp = lane >> 2, tg = lane & 3;
    int wm = warp >> 1, wn = warp & 1; // 4m x 2n warps; warp tile 32 x 128

    float acc[2][16][4];
#pragma unroll
    for (int i = 0; i < 2; i++)
#pragma unroll
        for (int j = 0; j < 16; j++)
#pragma unroll
            for (int v = 0; v < 4; v++) acc[i][j][v] = 0.0f;

    auto issue = [&](int kt, int s) {
        int k0 = kt * 16;
        float* xd = xs + s * 3072;
        float* wd = ws + s * 6144;
#pragma unroll
        for (int j = 0; j < 2; j++) {
            int id = tid + j * 256;
            int r = id >> 2, c = id & 3;
            cpasync16(&xd[r * 24 + c * 4], &XP[(size_t)(rowBase + r) * DP + k0 + c * 4]);
        }
#pragma unroll
        for (int j = 0; j < 4; j++) {
            int id = tid + j * 256;
            int r = id >> 2, c = id & 3;
            cpasync16(&wd[r * 24 + c * 4], &W[(size_t)(colBase + r) * DP + k0 + c * 4]);
        }
        CP_COMMIT;
    };

    issue(0, 0);
    issue(1, 1);

    for (int kt = 0; kt < KT; kt++) {
        int s = kt % 3;
        if (kt + 1 < KT) { CP_WAIT1; } else { CP_WAIT0; }
        __syncthreads();
        float* xb = xs + s * 3072;
        float* wb = ws + s * 6144;
#pragma unroll
        for (int kk = 0; kk < 2; kk++) {
            uint32_t a[2][4];
#pragma unroll
            for (int mt = 0; mt < 2; mt++) {
                int ar = (wm * 32 + mt * 16 + gp) * 24 + kk * 8 + tg * 2;
                float2 lo = *(float2*)&xb[ar];
                float2 hi = *(float2*)&xb[ar + 8 * 24];
                a[mt][0] = __float_as_uint(lo.x);
                a[mt][1] = __float_as_uint(hi.x);
                a[mt][2] = __float_as_uint(lo.y);
                a[mt][3] = __float_as_uint(hi.y);
            }
#pragma unroll
            for (int nt = 0; nt < 16; nt++) {
                int br = (wn * 128 + nt * 8 + gp) * 24 + kk * 8 + tg * 2;
                float2 bv = *(float2*)&wb[br];
                uint32_t b[2] = {__float_as_uint(bv.x), __float_as_uint(bv.y)};
#pragma unroll
                for (int mt = 0; mt < 2; mt++) mma_tf32(acc[mt][nt], a[mt], b);
            }
        }
        if (kt + 2 < KT) issue(kt + 2, (kt + 2) % 3);
        __syncthreads();
    }

#pragma unroll
    for (int mt = 0; mt < 2; mt++)
#pragma unroll
        for (int nt = 0; nt < 16; nt++) {
            int r0 = rowBase + wm * 32 + mt * 16 + gp;
            int col = colBase + wn * 128 + nt * 8 + 2 * tg;
            float bx = bias[col], by = bias[col + 1];
            int tt0 = r0 & 127, bb0 = r0 >> 7;
            *(float2*)&XG[((size_t)tt0 * B_SZ + bb0) * G + col] =
                make_float2(acc[mt][nt][0] + bx, acc[mt][nt][1] + by);
            int r1 = r0 + 8;
            int tt1 = r1 & 127, bb1 = r1 >> 7;
            *(float2*)&XG[((size_t)tt1 * B_SZ + bb1) * G + col] =
                make_float2(acc[mt][nt][2] + bx, acc[mt][nt][3] + by);
        }
}

__global__ __launch_bounds__(256) void proj_all_kernel() {
    extern __shared__ __align__(16) float psm[];
    float* xs = psm;            // 3 x 128x24
    float* ws = psm + 3 * 3072; // 3 x 256x24
    int bx = blockIdx.x;
    int rowBase = blockIdx.y * 128;
    if (bx < 4) {
        proj_impl(g_xp0, g_wih0, g_bias0, g_xg0, 304, 1024, 19, bx * 256, rowBase, xs, ws);
    } else if (bx == 4) {
        proj_impl(g_xp1, g_wih1, g_bias1, g_xg1, 80, 256, 5, 0, rowBase, xs, ws);
    } else {
        proj_impl(g_xp2, g_wih2, g_bias2, g_xg2, 48, 256, 3, 0, rowBase, xs, ws);
    }
}

// ---------------- launch 4: persistent recurrence ----------------
// blocks 0..127  : m0, block = 32 batch rows x 128 gate cols; per-bm 8-block barrier
// blocks 128..143: m1/m2, block = 64 batch rows x all 256 gate cols; fully independent
__global__ __launch_bounds__(256, 1) void persist_kernel() {
    extern __shared__ __align__(16) float sm[];
    int bid = blockIdx.x, tid = threadIdx.x;
    int lane = tid & 31, warp = tid >> 5;
    int gp = lane >> 2, tg = lane & 3;

    if (bid < 128) {
        // ================= module 0: H=256, G=1024 =================
        int bm = bid >> 3, bn = bid & 7;
        int rowBase = bm * 32, colBase = bn * 128;
        float* hs   = sm;                  // 32 x 264
        float* xbuf = sm + 8448;           // 32 x 128
        float* gsm  = sm + 8448 + 4096;    // 32 x 128

        // weights resident in registers: warp owns cols [wn*16, wn*16+16), all K
        int wn = warp;
        uint32_t breg[32][2][2];
#pragma unroll
        for (int kk = 0; kk < 32; kk++)
#pragma unroll
            for (int nt = 0; nt < 2; nt++) {
                float2 v = *(const float2*)
                    &g_whh0[(size_t)(colBase + wn * 16 + nt * 8 + gp) * 256 + kk * 8 + tg * 2];
                breg[kk][nt][0] = __float_as_uint(v.x);
                breg[kk][nt][1] = __float_as_uint(v.y);
            }

        float creg[4] = {0.0f, 0.0f, 0.0f, 0.0f};
        unsigned* cnt = &g_bar0[bm * 32];

        for (int t = 0; t < T_SZ; t++) {
            const float* hin = g_h0[t & 1];
            float* hout = g_h0[(t & 1) ^ 1];
            const float* xg = g_xg0 + (size_t)t * B_SZ * 1024;

            // group A: h (cg, needed for MMA). group B: xg (cold DRAM; hides under MMA)
#pragma unroll
            for (int j = 0; j < 8; j++) {
                int id = tid + j * 256;
                int r = id >> 6, c = id & 63;
                cpasync16cg(&hs[r * 264 + c * 4], &hin[(rowBase + r) * 256 + c * 4]);
            }
            CP_COMMIT;
#pragma unroll
            for (int j = 0; j < 4; j++) {
                int id = tid + j * 256;
                int r = id >> 5, c = id & 31;
                cpasync16(&xbuf[r * 128 + c * 4],
                          &xg[(size_t)(rowBase + r) * 1024 + colBase + c * 4]);
            }
            CP_COMMIT;
            CP_WAIT1; // h arrived; xg still in flight
            __syncthreads();

            float acc[2][2][4];
#pragma unroll
            for (int i = 0; i < 2; i++)
#pragma unroll
                for (int j = 0; j < 2; j++)
#pragma unroll
                    for (int v = 0; v < 4; v++) acc[i][j][v] = 0.0f;

#pragma unroll
            for (int kk = 0; kk < 32; kk++) {
                int kb = kk * 8 + tg * 2;
                float2 lo0 = *(float2*)&hs[gp * 264 + kb];
                float2 hi0 = *(float2*)&hs[(gp + 8) * 264 + kb];
                float2 lo1 = *(float2*)&hs[(gp + 16) * 264 + kb];
                float2 hi1 = *(float2*)&hs[(gp + 24) * 264 + kb];
                uint32_t a0[4] = {__float_as_uint(lo0.x), __float_as_uint(hi0.x),
                                  __float_as_uint(lo0.y), __float_as_uint(hi0.y)};
                uint32_t a1[4] = {__float_as_uint(lo1.x), __float_as_uint(hi1.x),
                                  __float_as_uint(lo1.y), __float_as_uint(hi1.y)};
                mma_tf32(acc[0][0], a0, breg[kk][0]);
                mma_tf32(acc[0][1], a0, breg[kk][1]);
                mma_tf32(acc[1][0], a1, breg[kk][0]);
                mma_tf32(acc[1][1], a1, breg[kk][1]);
            }

#pragma unroll
            for (int mt = 0; mt < 2; mt++)
#pragma unroll
                for (int nt = 0; nt < 2; nt++) {
                    int r = mt * 16 + gp, col = wn * 16 + nt * 8 + tg * 2;
                    *(float2*)&gsm[r * 128 + col] =
                        make_float2(acc[mt][nt][0], acc[mt][nt][1]);
                    *(float2*)&gsm[(r + 8) * 128 + col] =
                        make_float2(acc[mt][nt][2], acc[mt][nt][3]);
                }
            CP_WAIT0; // xg (long since arrived)
            __syncthreads();

#pragma unroll
            for (int j = 0; j < 4; j++) {
                int idx = tid + j * 256;
                int bl = idx >> 5, kl = idx & 31;
                float4 gt = *(float4*)&gsm[bl * 128 + 4 * kl];
                float4 xv = *(float4*)&xbuf[bl * 128 + 4 * kl];
                float ii = sigm(gt.x + xv.x);
                float ff = sigm(gt.y + xv.y);
                float gg = tanhfast(gt.z + xv.z);
                float oo = sigm(gt.w + xv.w);
                float cn = ff * creg[j] + ii * gg;
                creg[j] = cn;
                float hn = oo * tanhfast(cn);
                hout[(rowBase + bl) * 256 + swz(bn * 32 + kl)] = tf32r(hn);
            }

            if (t + 1 < T_SZ) {
                __syncthreads();
                if (tid == 0) {
                    __threadfence();
                    atomicAdd(cnt, 1u);
                    unsigned tgt = 8u * (unsigned)(t + 1);
                    while (*(volatile unsigned*)cnt < tgt) {}
                    __threadfence();
                }
                __syncthreads();
            }
        }
    } else {
        // ================= modules 1,2: H=64, G=256, fully independent ============
        int sub = bid - 128;
        int mod = sub >> 3, bm = sub & 7;
        int rowBase = bm * 64;
        const float* whh = mod ? g_whh2 : g_whh1;
        const float* xgb = mod ? g_xg2 : g_xg1;
        float* cb = mod ? g_c2 : g_c1;

        float* ws   = sm;                           // 256 x 72
        float* hs   = sm + 256 * 72;                // 64 x 72
        float* gsm  = sm + 256 * 72 + 64 * 72;      // 64 x 256
        float* xbuf = gsm + 64 * 256;               // 64 x 256

        for (int idx = tid; idx < 256 * 16; idx += 256) {
            int r = idx >> 4, c = idx & 15;
            *(float4*)&ws[r * 72 + c * 4] = *(const float4*)&whh[r * 64 + c * 4];
        }

        int wm = warp >> 2, wn = warp & 3;

        for (int t = 0; t < T_SZ; t++) {
            const float* hin = mod ? g_h2[t & 1] : g_h1[t & 1];
            float* hout = mod ? g_h2[(t & 1) ^ 1] : g_h1[(t & 1) ^ 1];
            const float* xg = xgb + (size_t)t * B_SZ * 256;

            // group A: h. group B: xg (waits deferred past MMA)
#pragma unroll
            for (int j = 0; j < 4; j++) {
                int id = tid + j * 256;
                int r = id >> 4, c = id & 15;
                cpasync16cg(&hs[r * 72 + c * 4], &hin[(rowBase + r) * 64 + c * 4]);
            }
            CP_COMMIT;
#pragma unroll
            for (int j = 0; j < 16; j++) {
                int id = tid + j * 256;
                int r = id >> 6, c = id & 63;
                cpasync16(&xbuf[r * 256 + c * 4],
                          &xg[(size_t)(rowBase + r) * 256 + c * 4]);
            }
            CP_COMMIT;
            CP_WAIT1;
            __syncthreads();

            float acc[2][8][4];
#pragma unroll
            for (int i = 0; i < 2; i++)
#pragma unroll
                for (int j = 0; j < 8; j++)
#pragma unroll
                    for (int v = 0; v < 4; v++) acc[i][j][v] = 0.0f;

#pragma unroll
            for (int kk = 0; kk < 8; kk++) {
                uint32_t a[2][4];
#pragma unroll
                for (int mt = 0; mt < 2; mt++) {
                    int ar = (wm * 32 + mt * 16 + gp) * 72 + kk * 8 + tg * 2;
                    float2 lo = *(float2*)&hs[ar];
                    float2 hi = *(float2*)&hs[ar + 8 * 72];
                    a[mt][0] = __float_as_uint(lo.x);
                    a[mt][1] = __float_as_uint(hi.x);
                    a[mt][2] = __float_as_uint(lo.y);
                    a[mt][3] = __float_as_uint(hi.y);
                }
#pragma unroll
                for (int nt = 0; nt < 8; nt++) {
                    int br = (wn * 64 + nt * 8 + gp) * 72 + kk * 8 + tg * 2;
                    float2 bv = *(float2*)&ws[br];
                    uint32_t b[2] = {__float_as_uint(bv.x), __float_as_uint(bv.y)};
#pragma unroll
                    for (int mt = 0; mt < 2; mt++) mma_tf32(acc[mt][nt], a[mt], b);
                }
            }

#pragma unroll
            for (int mt = 0; mt < 2; mt++)
#pragma unroll
                for (int nt = 0; nt < 8; nt++) {
                    int r = wm * 32 + mt * 16 + gp;
                    int col = wn * 64 + nt * 8 + 2 * tg;
                    *(float2*)&gsm[r * 256 + col] = make_float2(acc[mt][nt][0], acc[mt][nt][1]);
                    *(float2*)&gsm[(r + 8) * 256 + col] = make_float2(acc[mt][nt][2], acc[mt][nt][3]);
                }
            CP_WAIT0;
            __syncthreads();

            for (int idx = tid; idx < 4096; idx += 256) {
                int kl = idx & 63, bl = idx >> 6;
                float4 gt = *(float4*)&gsm[bl * 256 + 4 * kl];
                int bg = rowBase + bl;
                float4 xv = *(float4*)&xbuf[bl * 256 + 4 * kl];
                float ii = sigm(gt.x + xv.x);
                float ff = sigm(gt.y + xv.y);
                float gg = tanhfast(gt.z + xv.z);
                float oo = sigm(gt.w + xv.w);
                float cold = cb[bg * 64 + kl];
                float cn = ff * cold + ii * gg;
                float hn = oo * tanhfast(cn);
                cb[bg * 64 + kl] = cn;
                hout[bg * 64 + swz(kl)] = tf32r(hn);
            }
            __syncthreads();
        }
    }
}

// ---------------- launch 5: head ----------------
__global__ void head_kernel(const float* __restrict__ w1, const float* __restrict__ b1,
                            const float* __restrict__ w2, const float* __restrict__ b2,
                            float* __restrict__ out) {
    __shared__ float hc[8 * 384];
    __shared__ float red[256];
    int tid = threadIdx.x;
    int rowBase = blockIdx.x * 8;

    for (int i = tid; i < 8 * 384; i += 256) {
        int r = i / 384, d = i - r * 384;
        int bg = rowBase + r;
        float v;
        if (d < 256)      v = g_h0[0][bg * 256 + swz(d)];
        else if (d < 320) v = g_h1[0][bg * 64 + swz(d - 256)];
        else              v = g_h2[0][bg * 64 + swz(d - 320)];
        hc[i] = v;
    }
    __syncthreads();

    for (int pass = 0; pass < 2; pass++) {
        int row = pass * 4 + (tid >> 6);
        int cell = tid & 63;
        const float* wr = w1 + cell * 384;
        const float* hr = hc + row * 384;
        float a = b1[cell];
#pragma unroll 4
        for (int d = 0; d < 384; d++) a += hr[d] * wr[d];
        a = fmaxf(a, 0.0f);
        red[tid] = a * w2[cell];
        __syncthreads();
        if (cell == 0) {
            float s = 0.0f;
#pragma unroll
            for (int j = 0; j < 64; j++) s += red[tid + j];
            out[rowBase + row] = s + b2[0];
        }
        __syncthreads();
    }
}

// ---------------- launch ----------------
extern "C" void kernel_launch(void* const* d_in, const int* in_sizes, int n_in,
                              void* d_out, int out_size) {
    const float* x0    = (const float*)d_in[0];
    const float* x1    = (const float*)d_in[1];
    const float* x2    = (const float*)d_in[2];
    const float* w_ih0 = (const float*)d_in[3];
    const float* w_hh0 = (const float*)d_in[4];
    const float* b_ih0 = (const float*)d_in[5];
    const float* b_hh0 = (const float*)d_in[6];
    const float* w_ih1 = (const float*)d_in[7];
    const float* w_hh1 = (const float*)d_in[8];
    const float* b_ih1 = (const float*)d_in[9];
    const float* b_hh1 = (const float*)d_in[10];
    const float* w_ih2 = (const float*)d_in[11];
    const float* w_hh2 = (const float*)d_in[12];
    const float* b_ih2 = (const float*)d_in[13];
    const float* b_hh2 = (const float*)d_in[14];
    const float* w1    = (const float*)d_in[15];
    const float* b1    = (const float*)d_in[16];
    const float* w2    = (const float*)d_in[17];
    const float* b2    = (const float*)d_in[18];
    float* out = (float*)d_out;

    cudaFuncSetAttribute(persist_kernel, cudaFuncAttributeMaxDynamicSharedMemorySize,
                         SMEM_PERSIST);
    cudaFuncSetAttribute(proj_all_kernel, cudaFuncAttributeMaxDynamicSharedMemorySize,
                         SMEM_PROJ);

    // launch 0
    prep_w_kernel<<<512, 256>>>(w_ih0, w_hh0, b_ih0, b_hh0,
                                w_ih1, w_hh1, b_ih1, b_hh1,
                                w_ih2, w_hh2, b_ih2, b_hh2);
    // launch 1
    prep_x_kernel<<<1024, 256>>>(x0, x1, x2);
    // launch 2
    init_kernel<<<256, 256>>>();
    // launch 3  (ncu capture index) — the projection GEMM
    proj_all_kernel<<<dim3(6, 512), 256, SMEM_PROJ>>>();
    // launch 4
    persist_kernel<<<NBLK, 256, SMEM_PERSIST>>>();
    // launch 5
    head_kernel<<<64, 256>>>(w1, b1, w2, b2, out);
}